// round 10
// baseline (speedup 1.0000x reference)
#include <cuda_runtime.h>
#include <cuda_bf16.h>
#include <cstdint>
#include <math.h>

#define B_ROWS 8192
#define HID    2048
#define INP    2048
#define NCLS   10
#define POOLK  45
#define NF     45
#define ESTD   270
#define WLD    2318   // W_lin leading dim (HID + ESTD)
#define NTILE  (HID / 128)   // 16 N-tiles

// ---- GEMM tiling (R6 shape: measured optimum) ----
#define BM 128
#define BN 128
#define BKS 32               // K per stage
#define NSTG_IT (INP / BKS)  // 64 stage iterations
#define LDK 36               // padded floats per smem row
#define SA_FLOATS (BM * LDK)           // 4608
#define SB_FLOATS (BN * LDK)           // 4608
#define STAGE_FLOATS (SA_FLOATS + SB_FLOATS)   // 9216 (36864 B)
#define NSTAGE 3
#define GEMM_SMEM_BYTES (NSTAGE * STAGE_FLOATS * 4)   // 110592 B -> 2 CTAs/SM
#define NTHREADS 256          // 8 warps: 2 M-groups x 4 N-groups, warp tile 64x32

// epilogue smem overlay (floats, within dsm)
#define STG_STRIDE 136       // transposed stage [col][row], 136 ≡ 8 mod 32 -> see lane maps
#define STG_FLOATS_EP (128 * STG_STRIDE)       // 17408
#define SWL_OFF  STG_FLOATS_EP                 // 10 x 128 = 1280
#define LGH_OFF  (SWL_OFF + NCLS * 128)        // 128 x 10 = 1280
// total 19968 floats = 79.9 KB < 110.6 KB ✓

// Scratch (device globals — no runtime allocation)
__device__ float  g_Wl[NCLS * HID];              // W_lin[:, :2048] packed
__device__ float  g_WlE[NCLS * 288];             // W_lin[:, 2048:] packed (stride 288)
__device__ float  g_lg_part[(size_t)NTILE * B_ROWS * NCLS];   // per-tile logits partials
__device__ float  g_pool_part[(size_t)NTILE * B_ROWS * NF];   // per-tile pool partials
__device__ float2 g_cs[B_ROWS * NF];

// ------------------------------------------------------------------
__device__ __forceinline__ uint32_t smem_u32(const void* p) {
    return (uint32_t)__cvta_generic_to_shared(p);
}
__device__ __forceinline__ void cp16(uint32_t dst, const void* src) {
    asm volatile("cp.async.cg.shared.global [%0], [%1], 16;\n" :: "r"(dst), "l"(src));
}
__device__ __forceinline__ void ldsm_x4(uint32_t& r0, uint32_t& r1, uint32_t& r2,
                                        uint32_t& r3, uint32_t addr) {
    asm volatile("ldmatrix.sync.aligned.m8n8.x4.shared.b16 {%0,%1,%2,%3}, [%4];"
                 : "=r"(r0), "=r"(r1), "=r"(r2), "=r"(r3) : "r"(addr));
}
__device__ __forceinline__ void mma_tf32(float* d, const uint32_t* a,
                                         uint32_t b0, uint32_t b1) {
    asm volatile(
        "mma.sync.aligned.m16n8k8.row.col.f32.tf32.tf32.f32 "
        "{%0,%1,%2,%3}, {%4,%5,%6,%7}, {%8,%9}, {%0,%1,%2,%3};"
        : "+f"(d[0]), "+f"(d[1]), "+f"(d[2]), "+f"(d[3])
        : "r"(a[0]), "r"(a[1]), "r"(a[2]), "r"(a[3]), "r"(b0), "r"(b1));
}
__device__ __forceinline__ float tanh_fast(float x) {
    float r;
    asm("tanh.approx.f32 %0, %1;" : "=f"(r) : "f"(x));
    return r;
}

// ------------------------------------------------------------------
// Kernel 0 (x3 slices): pack W_lin into aligned buffers
// ------------------------------------------------------------------
#define PREP_N (NCLS * HID + NCLS * ESTD)   // 23180
#define PREP_CH 7936
__global__ __launch_bounds__(256) void prep_wl_kernel(
    const float* __restrict__ Wl, int phase)
{
    int idx = phase * PREP_CH + blockIdx.x * 256 + threadIdx.x;
    int hi = (phase + 1) * PREP_CH; if (hi > PREP_N) hi = PREP_N;
    if (idx >= hi) return;
    int n1 = NCLS * HID;
    if (idx < n1) {
        int c = idx / HID, k = idx % HID;
        g_Wl[idx] = Wl[(size_t)c * WLD + k];
    } else {
        int j = idx - n1;
        int c = j / ESTD, e = j % ESTD;
        g_WlE[c * 288 + e] = Wl[(size_t)c * WLD + HID + e];
    }
}

// ------------------------------------------------------------------
// Kernel 1: GEMM + tanh + FUSED pool/logits partials (g_Y eliminated)
// CTA 128x128, 8 warps (2M x 4N), warp tile 64x32, 3-stage cp.async, 2 CTAs/SM
// ------------------------------------------------------------------
__device__ __forceinline__ void load_stage(
    float* sbase, const float* __restrict__ Ax, const float* __restrict__ Bw,
    int bm, int bn, int kt, int tid)
{
    uint32_t su = smem_u32(sbase);
    #pragma unroll
    for (int i = 0; i < 4; i++) {
        int ci = tid + i * NTHREADS;
        int r = ci >> 3, ko = (ci & 7) << 2;
        cp16(su + (uint32_t)(r * LDK + ko) * 4,
             Ax + (size_t)(bm + r) * INP + kt + ko);
    }
    uint32_t sub = su + SA_FLOATS * 4;
    #pragma unroll
    for (int i = 0; i < 4; i++) {
        int ci = tid + i * NTHREADS;
        int r = ci >> 3, ko = (ci & 7) << 2;
        cp16(sub + (uint32_t)(r * LDK + ko) * 4,
             Bw + (size_t)(bn + r) * INP + kt + ko);
    }
    asm volatile("cp.async.commit_group;" ::: "memory");
}

__global__ __launch_bounds__(NTHREADS, 2) void gemm_tanh_kernel(
    const float* __restrict__ x, const float* __restrict__ W,
    const float* __restrict__ b_ih, const float* __restrict__ b_hh)
{
    extern __shared__ float dsm[];
    __shared__ float sbias[BN];

    const int tid  = threadIdx.x;
    const int warp = tid >> 5;
    const int lane = tid & 31;
    const int qid  = lane >> 2;   // 0..7
    const int tq   = lane & 3;    // 0..3
    const int bm = blockIdx.y * BM;
    const int bn = blockIdx.x * BN;

    if (tid < BN) sbias[tid] = b_ih[bn + tid] + b_hh[bn + tid];

    const int wm = (warp & 1) * 64;    // 2 warps along M
    const int wn = (warp >> 1) * 32;   // 4 warps along N

    // ldmatrix source selectors (b16-as-tf32 trick)
    const int rsel = ((lane >> 3) & 1) * 8 + (lane & 7);
    const int csel = (lane >> 4) * 4;

    float acc[4][4][4];
    #pragma unroll
    for (int mf = 0; mf < 4; mf++)
        #pragma unroll
        for (int nf = 0; nf < 4; nf++)
            #pragma unroll
            for (int e = 0; e < 4; e++) acc[mf][nf][e] = 0.f;

    load_stage(dsm,                x, W, bm, bn, 0,   tid);
    load_stage(dsm + STAGE_FLOATS, x, W, bm, bn, BKS, tid);

    int sidx = 0;
    for (int s = 0; s < NSTG_IT; s++) {
        if (s == NSTG_IT - 1)
            asm volatile("cp.async.wait_group 0;" ::: "memory");
        else
            asm volatile("cp.async.wait_group 1;" ::: "memory");
        __syncthreads();

        if (s + 2 < NSTG_IT) {
            int nidx = sidx + 2; if (nidx >= NSTAGE) nidx -= NSTAGE;
            load_stage(dsm + nidx * STAGE_FLOATS, x, W, bm, bn, (s + 2) * BKS, tid);
        }

        float* sA = dsm + sidx * STAGE_FLOATS;
        uint32_t sAu = smem_u32(sA);
        const uint32_t* sB = (const uint32_t*)(sA + SA_FLOATS);

        #pragma unroll
        for (int kk = 0; kk < BKS; kk += 8) {
            uint32_t a[4][4], b[4][2];
            #pragma unroll
            for (int mf = 0; mf < 4; mf++) {
                uint32_t addr = sAu +
                    (uint32_t)((wm + mf * 16 + rsel) * LDK + kk + csel) * 4;
                ldsm_x4(a[mf][0], a[mf][1], a[mf][2], a[mf][3], addr);
            }
            #pragma unroll
            for (int nf = 0; nf < 4; nf++) {
                int rowb = (wn + nf * 8 + qid) * LDK + kk + tq;
                b[nf][0] = sB[rowb];
                b[nf][1] = sB[rowb + 4];
            }
            #pragma unroll
            for (int mf = 0; mf < 4; mf++)
                #pragma unroll
                for (int nf = 0; nf < 4; nf++)
                    mma_tf32(acc[mf][nf], a[mf], b[nf][0], b[nf][1]);
        }

        if (++sidx >= NSTAGE) sidx = 0;
    }

    // ---------- fused epilogue ----------
    __syncthreads();   // all MMAs done before dsm is reused as staging

    float* stg  = dsm;               // transposed tile: stg[col*136 + row]
    float* sWl  = dsm + SWL_OFF;     // [class][128]
    float* lghf = dsm + LGH_OFF;     // [row][10] halves

    // load W_lin slice for this N-tile
    for (int i = tid; i < NCLS * 128; i += NTHREADS)
        sWl[i] = g_Wl[(i >> 7) * HID + bn + (i & 127)];

    // stage tanh(acc + bias), transposed
    #pragma unroll
    for (int mf = 0; mf < 4; mf++) {
        int r0 = wm + mf * 16 + qid;   // local row
        #pragma unroll
        for (int nf = 0; nf < 4; nf++) {
            int lc = wn + nf * 8 + tq * 2;
            float b0 = sbias[lc], b1 = sbias[lc + 1];
            stg[lc * STG_STRIDE + r0]           = tanh_fast(acc[mf][nf][0] + b0);
            stg[(lc + 1) * STG_STRIDE + r0]     = tanh_fast(acc[mf][nf][1] + b1);
            stg[lc * STG_STRIDE + r0 + 8]       = tanh_fast(acc[mf][nf][2] + b0);
            stg[(lc + 1) * STG_STRIDE + r0 + 8] = tanh_fast(acc[mf][nf][3] + b1);
        }
    }
    __syncthreads();

    const int r    = tid & 127;
    const int half = tid >> 7;       // 0: cols 0-63, 1: cols 64-127
    const int j0   = half * 64;

    float lg[NCLS];
    #pragma unroll
    for (int c = 0; c < NCLS; c++) lg[c] = 0.f;
    for (int j = j0; j < j0 + 64; j++) {
        float y = stg[j * STG_STRIDE + r];     // consecutive rows across lanes: conflict-free
        #pragma unroll
        for (int c = 0; c < NCLS; c++) lg[c] += y * sWl[c * 128 + j];  // broadcast
    }
    if (half) {
        #pragma unroll
        for (int c = 0; c < NCLS; c++) lghf[r * NCLS + c] = lg[c];
    }
    __syncthreads();

    const int tileN = bn >> 7;
    if (!half) {
        #pragma unroll
        for (int c = 0; c < NCLS; c++) lg[c] += lghf[r * NCLS + c];
        float* dst = &g_lg_part[((size_t)tileN * B_ROWS + bm + r) * NCLS];
        #pragma unroll
        for (int c = 0; c < NCLS; c++) dst[c] = lg[c];
    } else {
        // pool partials: features intersecting this 128-col tile
        int f0 = bn / POOLK;
        int f1 = (bn + 127) / POOLK; if (f1 > NF - 1) f1 = NF - 1;
        for (int f = f0; f <= f1; f++) {
            int c0 = POOLK * f - bn, c1 = c0 + POOLK - 1;
            if (c0 < 0) c0 = 0;
            if (c1 > 127) c1 = 127;
            float sum = 0.f;
            for (int c = c0; c <= c1; c++) sum += stg[c * STG_STRIDE + r];
            g_pool_part[((size_t)tileN * B_ROWS + bm + r) * NF + f] = sum;
        }
    }
}

// ------------------------------------------------------------------
// Kernel 2: per-feature inclusive scan of (v, v^2) over batch
// v assembled from the <=2 per-tile pool partials, /45
// ------------------------------------------------------------------
__global__ __launch_bounds__(256) void scan_kernel()
{
    const int f = blockIdx.x;
    const int t = threadIdx.x, lane = t & 31, w = t >> 5;
    const int t0 = (POOLK * f) >> 7;
    const int t1 = (POOLK * f + POOLK - 1) >> 7;
    __shared__ float2 wtot[8];
    float2 carry = make_float2(0.f, 0.f);

    for (int chunk = 0; chunk < B_ROWS / 256; chunk++) {
        int i = chunk * 256 + t;
        float v = g_pool_part[((size_t)t0 * B_ROWS + i) * NF + f];
        if (t1 != t0) v += g_pool_part[((size_t)t1 * B_ROWS + i) * NF + f];
        v *= (1.0f / (float)POOLK);
        float2 s = make_float2(v, v * v);
        #pragma unroll
        for (int off = 1; off < 32; off <<= 1) {
            float a  = __shfl_up_sync(0xffffffffu, s.x, off);
            float b2 = __shfl_up_sync(0xffffffffu, s.y, off);
            if (lane >= off) { s.x += a; s.y += b2; }
        }
        if (lane == 31) wtot[w] = s;
        __syncthreads();
        if (w == 0 && lane < 8) {
            float2 xx = wtot[lane];
            #pragma unroll
            for (int off = 1; off < 8; off <<= 1) {
                float a  = __shfl_up_sync(0xffu, xx.x, off);
                float b2 = __shfl_up_sync(0xffu, xx.y, off);
                if (lane >= off) { xx.x += a; xx.y += b2; }
            }
            wtot[lane] = xx;
        }
        __syncthreads();
        float2 pre = carry;
        if (w > 0) { pre.x += wtot[w - 1].x; pre.y += wtot[w - 1].y; }
        g_cs[i * NF + f] = make_float2(s.x + pre.x, s.y + pre.y);
        carry.x += wtot[7].x;
        carry.y += wtot[7].y;
        __syncthreads();
    }
}

// ------------------------------------------------------------------
// Kernel 3: final — sum 16 logits partials + est-part + softmax
// ------------------------------------------------------------------
__global__ __launch_bounds__(256) void final_kernel(
    const float* __restrict__ b_lin, float* __restrict__ out)
{
    const int t = threadIdx.x, lane = t & 31, wid = t >> 5;
    __shared__ float est_s[8][272];
    __shared__ float sl[8][NCLS];

    for (int e = t; e < 8 * ESTD; e += 256) {
        int r = e / ESTD, e2 = e % ESTD;
        int f = e2 / 6, rem = e2 % 6, j = rem >> 1, sflag = rem & 1;
        int L = (j == 0) ? 32 : (j == 1) ? 128 : 512;
        int bb = blockIdx.x * 8 + r;
        float2 c1 = g_cs[bb * NF + f];
        float2 c0 = (bb >= L) ? g_cs[(bb - L) * NF + f] : make_float2(0.f, 0.f);
        float cnt = fminf((float)(bb + 1), (float)L);
        float m = (c1.x - c0.x) / cnt;
        est_s[r][e2] = (sflag == 0) ? m : ((c1.y - c0.y) / cnt - m * m);
    }
    __syncthreads();

    const int row = blockIdx.x * 8 + wid;
    if (lane < NCLS) {
        int c = lane;
        float lg = b_lin[c];
        #pragma unroll
        for (int tl = 0; tl < NTILE; tl++)
            lg += g_lg_part[((size_t)tl * B_ROWS + row) * NCLS + c];
        const float* We = &g_WlE[c * 288];
        for (int e = 0; e < ESTD; e++) lg += est_s[wid][e] * We[e];
        sl[wid][c] = lg;
    }
    __syncwarp();
    if (lane == 0) {
        float mx = -1e30f;
        #pragma unroll
        for (int c = 0; c < NCLS; c++) mx = fmaxf(mx, sl[wid][c]);
        float ex[NCLS], sum = 0.f;
        #pragma unroll
        for (int c = 0; c < NCLS; c++) { ex[c] = expf(sl[wid][c] - mx); sum += ex[c]; }
        float inv = 1.0f / sum;
        #pragma unroll
        for (int c = 0; c < NCLS; c++) out[row * NCLS + c] = ex[c] * inv;
    }
}

// ------------------------------------------------------------------
extern "C" void kernel_launch(void* const* d_in, const int* in_sizes, int n_in,
                              void* d_out, int out_size)
{
    (void)in_sizes; (void)n_in; (void)out_size;
    const float* x     = (const float*)d_in[0];
    const float* W_ih  = (const float*)d_in[1];
    // d_in[2] = W_hh — dead: seq_len==1 and h0==0
    const float* b_ih  = (const float*)d_in[3];
    const float* b_hh  = (const float*)d_in[4];
    const float* W_lin = (const float*)d_in[5];
    const float* b_lin = (const float*)d_in[6];
    float* out = (float*)d_out;

    cudaFuncSetAttribute(gemm_tanh_kernel,
                         cudaFuncAttributeMaxDynamicSharedMemorySize, GEMM_SMEM_BYTES);

    // GEMM kept as 4th launch (ncu capture slot)
    int pb = (PREP_CH + 255) / 256;
    prep_wl_kernel<<<pb, 256>>>(W_lin, 0);
    prep_wl_kernel<<<pb, 256>>>(W_lin, 1);
    prep_wl_kernel<<<pb, 256>>>(W_lin, 2);

    dim3 g1(HID / BN, B_ROWS / BM);   // 16 x 64 = 1024 CTAs, 2 per SM
    gemm_tanh_kernel<<<g1, NTHREADS, GEMM_SMEM_BYTES>>>(x, W_ih, b_ih, b_hh);

    scan_kernel<<<NF, 256>>>();
    final_kernel<<<B_ROWS / 8, 256>>>(b_lin, out);
}

// round 11
// speedup vs baseline: 1.1881x; 1.1881x over previous
#include <cuda_runtime.h>
#include <cuda_bf16.h>
#include <cstdint>
#include <math.h>

#define B_ROWS 8192
#define HID    2048
#define INP    2048
#define NCLS   10
#define POOLK  45
#define NF     45
#define ESTD   270
#define WLD    2318   // W_lin leading dim (HID + ESTD)
#define NTILE  (HID / 128)   // 16 N-tiles

// ---- GEMM tiling (R6 shape: measured optimum) ----
#define BM 128
#define BN 128
#define BKS 32               // K per stage
#define NSTG_IT (INP / BKS)  // 64 stage iterations
#define LDK 36               // padded floats per smem row
#define SA_FLOATS (BM * LDK)           // 4608
#define SB_FLOATS (BN * LDK)           // 4608
#define STAGE_FLOATS (SA_FLOATS + SB_FLOATS)   // 9216 (36864 B)
#define NSTAGE 3
#define GEMM_SMEM_BYTES (NSTAGE * STAGE_FLOATS * 4)   // 110592 B -> 2 CTAs/SM
#define NTHREADS 256          // 8 warps: 2 M-groups x 4 N-groups, warp tile 64x32

// epilogue smem overlay (floats, within dsm)
#define STG_STRIDE 136       // transposed stage [col][row]
#define STG_FLOATS_EP (128 * STG_STRIDE)       // 17408
#define SWL_OFF  STG_FLOATS_EP                 // 10 x 128
#define LGH_OFF  (SWL_OFF + NCLS * 128)        // 128 x 10

// Scratch (device globals — no runtime allocation)
__device__ float  g_Wl[NCLS * HID];              // W_lin[:, :2048] packed
__device__ float  g_WlE[NCLS * 288];             // W_lin[:, 2048:] packed (stride 288)
__device__ float  g_lg_part[(size_t)NTILE * B_ROWS * NCLS];    // per-tile logits partials
__device__ float  g_pool_part[(size_t)NF * 2 * B_ROWS];        // [f][slot][row]
__device__ float2 g_cs[B_ROWS * NF];

// ------------------------------------------------------------------
__device__ __forceinline__ uint32_t smem_u32(const void* p) {
    return (uint32_t)__cvta_generic_to_shared(p);
}
__device__ __forceinline__ void cp16(uint32_t dst, const void* src) {
    asm volatile("cp.async.cg.shared.global [%0], [%1], 16;\n" :: "r"(dst), "l"(src));
}
__device__ __forceinline__ void ldsm_x4(uint32_t& r0, uint32_t& r1, uint32_t& r2,
                                        uint32_t& r3, uint32_t addr) {
    asm volatile("ldmatrix.sync.aligned.m8n8.x4.shared.b16 {%0,%1,%2,%3}, [%4];"
                 : "=r"(r0), "=r"(r1), "=r"(r2), "=r"(r3) : "r"(addr));
}
__device__ __forceinline__ void mma_tf32(float* d, const uint32_t* a,
                                         uint32_t b0, uint32_t b1) {
    asm volatile(
        "mma.sync.aligned.m16n8k8.row.col.f32.tf32.tf32.f32 "
        "{%0,%1,%2,%3}, {%4,%5,%6,%7}, {%8,%9}, {%0,%1,%2,%3};"
        : "+f"(d[0]), "+f"(d[1]), "+f"(d[2]), "+f"(d[3])
        : "r"(a[0]), "r"(a[1]), "r"(a[2]), "r"(a[3]), "r"(b0), "r"(b1));
}
__device__ __forceinline__ float tanh_fast(float x) {
    float r;
    asm("tanh.approx.f32 %0, %1;" : "=f"(r) : "f"(x));
    return r;
}

// ------------------------------------------------------------------
// Kernel 0 (x3 slices): pack W_lin into aligned buffers
// ------------------------------------------------------------------
#define PREP_N (NCLS * HID + NCLS * ESTD)   // 23180
#define PREP_CH 7936
__global__ __launch_bounds__(256) void prep_wl_kernel(
    const float* __restrict__ Wl, int phase)
{
    int idx = phase * PREP_CH + blockIdx.x * 256 + threadIdx.x;
    int hi = (phase + 1) * PREP_CH; if (hi > PREP_N) hi = PREP_N;
    if (idx >= hi) return;
    int n1 = NCLS * HID;
    if (idx < n1) {
        int c = idx / HID, k = idx % HID;
        g_Wl[idx] = Wl[(size_t)c * WLD + k];
    } else {
        int j = idx - n1;
        int c = j / ESTD, e = j % ESTD;
        g_WlE[c * 288 + e] = Wl[(size_t)c * WLD + HID + e];
    }
}

// ------------------------------------------------------------------
// Kernel 1: GEMM + tanh + FUSED pool/logits partials (g_Y eliminated)
// ------------------------------------------------------------------
__device__ __forceinline__ void load_stage(
    float* sbase, const float* __restrict__ Ax, const float* __restrict__ Bw,
    int bm, int bn, int kt, int tid)
{
    uint32_t su = smem_u32(sbase);
    #pragma unroll
    for (int i = 0; i < 4; i++) {
        int ci = tid + i * NTHREADS;
        int r = ci >> 3, ko = (ci & 7) << 2;
        cp16(su + (uint32_t)(r * LDK + ko) * 4,
             Ax + (size_t)(bm + r) * INP + kt + ko);
    }
    uint32_t sub = su + SA_FLOATS * 4;
    #pragma unroll
    for (int i = 0; i < 4; i++) {
        int ci = tid + i * NTHREADS;
        int r = ci >> 3, ko = (ci & 7) << 2;
        cp16(sub + (uint32_t)(r * LDK + ko) * 4,
             Bw + (size_t)(bn + r) * INP + kt + ko);
    }
    asm volatile("cp.async.commit_group;" ::: "memory");
}

__global__ __launch_bounds__(NTHREADS, 2) void gemm_tanh_kernel(
    const float* __restrict__ x, const float* __restrict__ W,
    const float* __restrict__ b_ih, const float* __restrict__ b_hh)
{
    extern __shared__ float dsm[];
    __shared__ float sbias[BN];

    const int tid  = threadIdx.x;
    const int warp = tid >> 5;
    const int lane = tid & 31;
    const int qid  = lane >> 2;
    const int tq   = lane & 3;
    const int bm = blockIdx.y * BM;
    const int bn = blockIdx.x * BN;

    if (tid < BN) sbias[tid] = b_ih[bn + tid] + b_hh[bn + tid];

    const int wm = (warp & 1) * 64;
    const int wn = (warp >> 1) * 32;
    const int rsel = ((lane >> 3) & 1) * 8 + (lane & 7);
    const int csel = (lane >> 4) * 4;

    float acc[4][4][4];
    #pragma unroll
    for (int mf = 0; mf < 4; mf++)
        #pragma unroll
        for (int nf = 0; nf < 4; nf++)
            #pragma unroll
            for (int e = 0; e < 4; e++) acc[mf][nf][e] = 0.f;

    load_stage(dsm,                x, W, bm, bn, 0,   tid);
    load_stage(dsm + STAGE_FLOATS, x, W, bm, bn, BKS, tid);

    int sidx = 0;
    for (int s = 0; s < NSTG_IT; s++) {
        if (s == NSTG_IT - 1)
            asm volatile("cp.async.wait_group 0;" ::: "memory");
        else
            asm volatile("cp.async.wait_group 1;" ::: "memory");
        __syncthreads();

        if (s + 2 < NSTG_IT) {
            int nidx = sidx + 2; if (nidx >= NSTAGE) nidx -= NSTAGE;
            load_stage(dsm + nidx * STAGE_FLOATS, x, W, bm, bn, (s + 2) * BKS, tid);
        }

        float* sA = dsm + sidx * STAGE_FLOATS;
        uint32_t sAu = smem_u32(sA);
        const uint32_t* sB = (const uint32_t*)(sA + SA_FLOATS);

        #pragma unroll
        for (int kk = 0; kk < BKS; kk += 8) {
            uint32_t a[4][4], b[4][2];
            #pragma unroll
            for (int mf = 0; mf < 4; mf++) {
                uint32_t addr = sAu +
                    (uint32_t)((wm + mf * 16 + rsel) * LDK + kk + csel) * 4;
                ldsm_x4(a[mf][0], a[mf][1], a[mf][2], a[mf][3], addr);
            }
            #pragma unroll
            for (int nf = 0; nf < 4; nf++) {
                int rowb = (wn + nf * 8 + qid) * LDK + kk + tq;
                b[nf][0] = sB[rowb];
                b[nf][1] = sB[rowb + 4];
            }
            #pragma unroll
            for (int mf = 0; mf < 4; mf++)
                #pragma unroll
                for (int nf = 0; nf < 4; nf++)
                    mma_tf32(acc[mf][nf], a[mf], b[nf][0], b[nf][1]);
        }

        if (++sidx >= NSTAGE) sidx = 0;
    }

    // ---------- fused epilogue ----------
    __syncthreads();

    float* stg  = dsm;               // transposed tile: stg[col*136 + row]
    float* sWl  = dsm + SWL_OFF;     // [class][128]
    float* lghf = dsm + LGH_OFF;     // [row][10] halves

    for (int i = tid; i < NCLS * 128; i += NTHREADS)
        sWl[i] = g_Wl[(i >> 7) * HID + bn + (i & 127)];

    #pragma unroll
    for (int mf = 0; mf < 4; mf++) {
        int r0 = wm + mf * 16 + qid;
        #pragma unroll
        for (int nf = 0; nf < 4; nf++) {
            int lc = wn + nf * 8 + tq * 2;
            float b0 = sbias[lc], b1 = sbias[lc + 1];
            stg[lc * STG_STRIDE + r0]           = tanh_fast(acc[mf][nf][0] + b0);
            stg[(lc + 1) * STG_STRIDE + r0]     = tanh_fast(acc[mf][nf][1] + b1);
            stg[lc * STG_STRIDE + r0 + 8]       = tanh_fast(acc[mf][nf][2] + b0);
            stg[(lc + 1) * STG_STRIDE + r0 + 8] = tanh_fast(acc[mf][nf][3] + b1);
        }
    }
    __syncthreads();

    const int r    = tid & 127;
    const int half = tid >> 7;
    const int j0   = half * 64;
    const int tileN = bn >> 7;

    float lg[NCLS];
    #pragma unroll
    for (int c = 0; c < NCLS; c++) lg[c] = 0.f;
    for (int j = j0; j < j0 + 64; j++) {
        float y = stg[j * STG_STRIDE + r];
        #pragma unroll
        for (int c = 0; c < NCLS; c++) lg[c] += y * sWl[c * 128 + j];
    }
    if (half) {
        #pragma unroll
        for (int c = 0; c < NCLS; c++) lghf[r * NCLS + c] = lg[c];
    }
    __syncthreads();

    if (!half) {
        #pragma unroll
        for (int c = 0; c < NCLS; c++) lg[c] += lghf[r * NCLS + c];
        float* dst = &g_lg_part[((size_t)tileN * B_ROWS + bm + r) * NCLS];
        #pragma unroll
        for (int c = 0; c < NCLS; c++) dst[c] = lg[c];
    } else {
        // pool partials -> [f][slot][row] for coalesced scan reads
        int f0 = bn / POOLK;
        int f1 = (bn + 127) / POOLK; if (f1 > NF - 1) f1 = NF - 1;
        for (int f = f0; f <= f1; f++) {
            int c0 = POOLK * f - bn, c1 = c0 + POOLK - 1;
            if (c0 < 0) c0 = 0;
            if (c1 > 127) c1 = 127;
            float sum = 0.f;
            for (int c = c0; c <= c1; c++) sum += stg[c * STG_STRIDE + r];
            int slot = (tileN == (POOLK * f) >> 7) ? 0 : 1;
            g_pool_part[((size_t)f * 2 + slot) * B_ROWS + bm + r] = sum;
        }
    }
}

// ------------------------------------------------------------------
// Kernel 2: per-feature inclusive scan of (v, v^2) over batch (coalesced)
// ------------------------------------------------------------------
__global__ __launch_bounds__(256) void scan_kernel()
{
    const int f = blockIdx.x;
    const int t = threadIdx.x, lane = t & 31, w = t >> 5;
    const bool two = ((POOLK * f) >> 7) != ((POOLK * f + POOLK - 1) >> 7);
    const float* P0 = &g_pool_part[(size_t)f * 2 * B_ROWS];
    const float* P1 = P0 + B_ROWS;
    __shared__ float2 wtot[8];
    float2 carry = make_float2(0.f, 0.f);

    for (int chunk = 0; chunk < B_ROWS / 256; chunk++) {
        int i = chunk * 256 + t;
        float v = P0[i];
        if (two) v += P1[i];
        v *= (1.0f / (float)POOLK);
        float2 s = make_float2(v, v * v);
        #pragma unroll
        for (int off = 1; off < 32; off <<= 1) {
            float a  = __shfl_up_sync(0xffffffffu, s.x, off);
            float b2 = __shfl_up_sync(0xffffffffu, s.y, off);
            if (lane >= off) { s.x += a; s.y += b2; }
        }
        if (lane == 31) wtot[w] = s;
        __syncthreads();
        if (w == 0 && lane < 8) {
            float2 xx = wtot[lane];
            #pragma unroll
            for (int off = 1; off < 8; off <<= 1) {
                float a  = __shfl_up_sync(0xffu, xx.x, off);
                float b2 = __shfl_up_sync(0xffu, xx.y, off);
                if (lane >= off) { xx.x += a; xx.y += b2; }
            }
            wtot[lane] = xx;
        }
        __syncthreads();
        float2 pre = carry;
        if (w > 0) { pre.x += wtot[w - 1].x; pre.y += wtot[w - 1].y; }
        g_cs[i * NF + f] = make_float2(s.x + pre.x, s.y + pre.y);
        carry.x += wtot[7].x;
        carry.y += wtot[7].y;
        __syncthreads();
    }
}

// ------------------------------------------------------------------
// Kernel 3: final — warp per row: sum 16 tile partials + est·WlE + softmax
// ------------------------------------------------------------------
__global__ __launch_bounds__(256) void final_kernel(
    const float* __restrict__ b_lin, float* __restrict__ out)
{
    const int t = threadIdx.x, lane = t & 31, wid = t >> 5;
    __shared__ float est_s[8][272];

    for (int e = t; e < 8 * ESTD; e += 256) {
        int r = e / ESTD, e2 = e % ESTD;
        int f = e2 / 6, rem = e2 % 6, j = rem >> 1, sflag = rem & 1;
        int L = (j == 0) ? 32 : (j == 1) ? 128 : 512;
        int bb = blockIdx.x * 8 + r;
        float2 c1 = g_cs[bb * NF + f];
        float2 c0 = (bb >= L) ? g_cs[(bb - L) * NF + f] : make_float2(0.f, 0.f);
        float cnt = fminf((float)(bb + 1), (float)L);
        float m = (c1.x - c0.x) / cnt;
        est_s[r][e2] = (sflag == 0) ? m : ((c1.y - c0.y) / cnt - m * m);
    }
    __syncthreads();

    const int row = blockIdx.x * 8 + wid;

    float acc[NCLS];
    #pragma unroll
    for (int c = 0; c < NCLS; c++) acc[c] = 0.f;

    // tile partials: 16 lanes each grab one tile's 10 floats
    if (lane < NTILE) {
        const float* p = &g_lg_part[((size_t)lane * B_ROWS + row) * NCLS];
        #pragma unroll
        for (int c = 0; c < NCLS; c++) acc[c] += p[c];
    }
    // est dot: lanes stride e
    for (int e = lane; e < ESTD; e += 32) {
        float ev = est_s[wid][e];
        #pragma unroll
        for (int c = 0; c < NCLS; c++) acc[c] += ev * g_WlE[c * 288 + e];
    }
    #pragma unroll
    for (int c = 0; c < NCLS; c++) {
        #pragma unroll
        for (int off = 16; off > 0; off >>= 1)
            acc[c] += __shfl_down_sync(0xffffffffu, acc[c], off);
    }
    if (lane == 0) {
        float lg[NCLS], mx = -1e30f;
        #pragma unroll
        for (int c = 0; c < NCLS; c++) { lg[c] = acc[c] + b_lin[c]; mx = fmaxf(mx, lg[c]); }
        float sum = 0.f;
        #pragma unroll
        for (int c = 0; c < NCLS; c++) { lg[c] = expf(lg[c] - mx); sum += lg[c]; }
        float inv = 1.0f / sum;
        #pragma unroll
        for (int c = 0; c < NCLS; c++) out[row * NCLS + c] = lg[c] * inv;
    }
}

// ------------------------------------------------------------------
extern "C" void kernel_launch(void* const* d_in, const int* in_sizes, int n_in,
                              void* d_out, int out_size)
{
    (void)in_sizes; (void)n_in; (void)out_size;
    const float* x     = (const float*)d_in[0];
    const float* W_ih  = (const float*)d_in[1];
    // d_in[2] = W_hh — dead: seq_len==1 and h0==0
    const float* b_ih  = (const float*)d_in[3];
    const float* b_hh  = (const float*)d_in[4];
    const float* W_lin = (const float*)d_in[5];
    const float* b_lin = (const float*)d_in[6];
    float* out = (float*)d_out;

    cudaFuncSetAttribute(gemm_tanh_kernel,
                         cudaFuncAttributeMaxDynamicSharedMemorySize, GEMM_SMEM_BYTES);

    // GEMM kept as 4th launch (ncu capture slot)
    int pb = (PREP_CH + 255) / 256;
    prep_wl_kernel<<<pb, 256>>>(W_lin, 0);
    prep_wl_kernel<<<pb, 256>>>(W_lin, 1);
    prep_wl_kernel<<<pb, 256>>>(W_lin, 2);

    dim3 g1(HID / BN, B_ROWS / BM);   // 16 x 64 = 1024 CTAs, 2 per SM
    gemm_tanh_kernel<<<g1, NTHREADS, GEMM_SMEM_BYTES>>>(x, W_ih, b_ih, b_hh);

    scan_kernel<<<NF, 256>>>();
    final_kernel<<<B_ROWS / 8, 256>>>(b_lin, out);
}

// round 12
// speedup vs baseline: 1.9047x; 1.6032x over previous
#include <cuda_runtime.h>
#include <cuda_bf16.h>
#include <cstdint>
#include <math.h>

#define B_ROWS 8192
#define HID    2048
#define INP    2048
#define NCLS   10
#define POOLK  45
#define NF     45
#define ESTD   270
#define WLD    2318   // W_lin leading dim (HID + ESTD)
#define NTILE  (HID / 128)   // 16 N-tiles

// ---- GEMM tiling: bf16 m16n8k16, CTA 128x128, warp tile 64x32 ----
#define BM 128
#define BN 128
#define BKS 64               // K (bf16 elems) per stage
#define NSTG_IT (INP / BKS)  // 32 stage iterations
#define LDKB 72              // padded bf16 per smem row (144 B, 16B-aligned)
#define SA_BYTES (BM * LDKB * 2)       // 18432
#define STAGE_BYTES (2 * SA_BYTES)     // 36864 (A + B)
#define NSTAGE 3
#define GEMM_SMEM_BYTES (NSTAGE * STAGE_BYTES)   // 110592 -> 2 CTAs/SM
#define NTHREADS 256          // 8 warps: 2M x 4N, warp tile 64x32

// epilogue smem overlay (floats, within dsm)
#define STG_STRIDE 136
#define STG_FLOATS_EP (128 * STG_STRIDE)
#define SWL_OFF  STG_FLOATS_EP
#define LGH_OFF  (SWL_OFF + NCLS * 128)
// 19968 floats = 79.9 KB < 110.6 KB ✓

// Scratch (device globals — no runtime allocation)
__device__ __nv_bfloat16 g_xb[(size_t)B_ROWS * INP];   // x in bf16 (RN)
__device__ __nv_bfloat16 g_wb[(size_t)HID * INP];      // W_ih in bf16 (RN)
__device__ float  g_Wl[NCLS * HID];
__device__ float  g_WlE[NCLS * 288];
__device__ float  g_lg_part[(size_t)NTILE * B_ROWS * NCLS];
__device__ float  g_pool_part[(size_t)NF * 2 * B_ROWS];
__device__ float2 g_cs[B_ROWS * NF];

// ------------------------------------------------------------------
__device__ __forceinline__ uint32_t smem_u32(const void* p) {
    return (uint32_t)__cvta_generic_to_shared(p);
}
__device__ __forceinline__ void cp16(uint32_t dst, const void* src) {
    asm volatile("cp.async.cg.shared.global [%0], [%1], 16;\n" :: "r"(dst), "l"(src));
}
__device__ __forceinline__ void ldsm_x4(uint32_t& r0, uint32_t& r1, uint32_t& r2,
                                        uint32_t& r3, uint32_t addr) {
    asm volatile("ldmatrix.sync.aligned.m8n8.x4.shared.b16 {%0,%1,%2,%3}, [%4];"
                 : "=r"(r0), "=r"(r1), "=r"(r2), "=r"(r3) : "r"(addr));
}
__device__ __forceinline__ void mma_bf16(float* d, const uint32_t* a,
                                         uint32_t b0, uint32_t b1) {
    asm volatile(
        "mma.sync.aligned.m16n8k16.row.col.f32.bf16.bf16.f32 "
        "{%0,%1,%2,%3}, {%4,%5,%6,%7}, {%8,%9}, {%0,%1,%2,%3};"
        : "+f"(d[0]), "+f"(d[1]), "+f"(d[2]), "+f"(d[3])
        : "r"(a[0]), "r"(a[1]), "r"(a[2]), "r"(a[3]), "r"(b0), "r"(b1));
}
__device__ __forceinline__ float tanh_fast(float x) {
    float r;
    asm("tanh.approx.f32 %0, %1;" : "=f"(r) : "f"(x));
    return r;
}

// ------------------------------------------------------------------
// Kernel 0a: fp32 -> bf16 (round-to-nearest)
// ------------------------------------------------------------------
__global__ __launch_bounds__(256) void cvt_bf16_kernel(
    const float* __restrict__ src, __nv_bfloat16* __restrict__ dst, int n4)
{
    int i = blockIdx.x * 256 + threadIdx.x;
    if (i >= n4) return;
    float4 v = ((const float4*)src)[i];
    __nv_bfloat162* d2 = (__nv_bfloat162*)dst;
    d2[2 * i]     = __floats2bfloat162_rn(v.x, v.y);
    d2[2 * i + 1] = __floats2bfloat162_rn(v.z, v.w);
}

// ------------------------------------------------------------------
// Kernel 0b: pack W_lin into aligned buffers
// ------------------------------------------------------------------
#define PREP_N (NCLS * HID + NCLS * ESTD)
__global__ __launch_bounds__(256) void prep_wl_kernel(const float* __restrict__ Wl)
{
    int idx = blockIdx.x * 256 + threadIdx.x;
    if (idx >= PREP_N) return;
    int n1 = NCLS * HID;
    if (idx < n1) {
        int c = idx / HID, k = idx % HID;
        g_Wl[idx] = Wl[(size_t)c * WLD + k];
    } else {
        int j = idx - n1;
        int c = j / ESTD, e = j % ESTD;
        g_WlE[c * 288 + e] = Wl[(size_t)c * WLD + HID + e];
    }
}

// ------------------------------------------------------------------
// Kernel 1: GEMM(bf16) + tanh + fused pool/logits partials
// ------------------------------------------------------------------
__device__ __forceinline__ void load_stage(char* sbase, int bm, int bn, int kt, int tid)
{
    uint32_t su = smem_u32(sbase);
    // A: 128 rows x 128 B (64 bf16) = 1024 x 16B chunks
    #pragma unroll
    for (int i = 0; i < 4; i++) {
        int ci = tid + i * NTHREADS;
        int r = ci >> 3, ko = (ci & 7) << 3;       // ko in bf16 elems (8 per 16B)
        cp16(su + (uint32_t)(r * LDKB + ko) * 2,
             g_xb + (size_t)(bm + r) * INP + kt + ko);
    }
    uint32_t sub = su + SA_BYTES;
    #pragma unroll
    for (int i = 0; i < 4; i++) {
        int ci = tid + i * NTHREADS;
        int r = ci >> 3, ko = (ci & 7) << 3;
        cp16(sub + (uint32_t)(r * LDKB + ko) * 2,
             g_wb + (size_t)(bn + r) * INP + kt + ko);
    }
    asm volatile("cp.async.commit_group;" ::: "memory");
}

__global__ __launch_bounds__(NTHREADS, 2) void gemm_tanh_kernel(
    const float* __restrict__ b_ih, const float* __restrict__ b_hh)
{
    extern __shared__ char dsmc[];
    float* dsm = (float*)dsmc;
    __shared__ float sbias[BN];

    const int tid  = threadIdx.x;
    const int warp = tid >> 5;
    const int lane = tid & 31;
    const int qid  = lane >> 2;
    const int tq   = lane & 3;
    const int bm = blockIdx.y * BM;
    const int bn = blockIdx.x * BN;

    if (tid < BN) sbias[tid] = b_ih[bn + tid] + b_hh[bn + tid];

    const int wm = (warp & 1) * 64;    // 2 warps along M
    const int wn = (warp >> 1) * 32;   // 4 warps along N

    // ldmatrix A selectors: lane -> row (l&15), k-half (l>>4)*8
    const int arow = lane & 15;
    const int akof = (lane >> 4) * 8;

    float acc[4][4][4];
    #pragma unroll
    for (int mf = 0; mf < 4; mf++)
        #pragma unroll
        for (int nf = 0; nf < 4; nf++)
            #pragma unroll
            for (int e = 0; e < 4; e++) acc[mf][nf][e] = 0.f;

    load_stage(dsmc,               bm, bn, 0,   tid);
    load_stage(dsmc + STAGE_BYTES, bm, bn, BKS, tid);

    int sidx = 0;
    for (int s = 0; s < NSTG_IT; s++) {
        if (s == NSTG_IT - 1)
            asm volatile("cp.async.wait_group 0;" ::: "memory");
        else
            asm volatile("cp.async.wait_group 1;" ::: "memory");
        __syncthreads();

        if (s + 2 < NSTG_IT) {
            int nidx = sidx + 2; if (nidx >= NSTAGE) nidx -= NSTAGE;
            load_stage(dsmc + nidx * STAGE_BYTES, bm, bn, (s + 2) * BKS, tid);
        }

        char* sA = dsmc + sidx * STAGE_BYTES;
        uint32_t sAu = smem_u32(sA);
        const uint32_t* sB = (const uint32_t*)(sA + SA_BYTES);

        #pragma unroll
        for (int kk = 0; kk < BKS; kk += 16) {
            uint32_t a[4][4], b[4][2];
            #pragma unroll
            for (int mf = 0; mf < 4; mf++) {
                uint32_t addr = sAu +
                    (uint32_t)((wm + mf * 16 + arow) * LDKB + kk + akof) * 2;
                ldsm_x4(a[mf][0], a[mf][1], a[mf][2], a[mf][3], addr);
            }
            #pragma unroll
            for (int nf = 0; nf < 4; nf++) {
                // word index: n*36 + kk/2 + tq  (LDKB=72 bf16 = 36 words)
                int roww = (wn + nf * 8 + qid) * (LDKB / 2) + (kk >> 1) + tq;
                b[nf][0] = sB[roww];
                b[nf][1] = sB[roww + 4];   // +8 bf16 = +4 words
            }
            #pragma unroll
            for (int mf = 0; mf < 4; mf++)
                #pragma unroll
                for (int nf = 0; nf < 4; nf++)
                    mma_bf16(acc[mf][nf], a[mf], b[nf][0], b[nf][1]);
        }

        if (++sidx >= NSTAGE) sidx = 0;
    }

    // ---------- fused epilogue (same acc layout as tf32 path) ----------
    __syncthreads();

    float* stg  = dsm;
    float* sWl  = dsm + SWL_OFF;
    float* lghf = dsm + LGH_OFF;

    for (int i = tid; i < NCLS * 128; i += NTHREADS)
        sWl[i] = g_Wl[(i >> 7) * HID + bn + (i & 127)];

    #pragma unroll
    for (int mf = 0; mf < 4; mf++) {
        int r0 = wm + mf * 16 + qid;
        #pragma unroll
        for (int nf = 0; nf < 4; nf++) {
            int lc = wn + nf * 8 + tq * 2;
            float b0 = sbias[lc], b1 = sbias[lc + 1];
            stg[lc * STG_STRIDE + r0]           = tanh_fast(acc[mf][nf][0] + b0);
            stg[(lc + 1) * STG_STRIDE + r0]     = tanh_fast(acc[mf][nf][1] + b1);
            stg[lc * STG_STRIDE + r0 + 8]       = tanh_fast(acc[mf][nf][2] + b0);
            stg[(lc + 1) * STG_STRIDE + r0 + 8] = tanh_fast(acc[mf][nf][3] + b1);
        }
    }
    __syncthreads();

    const int r    = tid & 127;
    const int half = tid >> 7;
    const int j0   = half * 64;
    const int tileN = bn >> 7;

    float lg[NCLS];
    #pragma unroll
    for (int c = 0; c < NCLS; c++) lg[c] = 0.f;
    for (int j = j0; j < j0 + 64; j++) {
        float y = stg[j * STG_STRIDE + r];
        #pragma unroll
        for (int c = 0; c < NCLS; c++) lg[c] += y * sWl[c * 128 + j];
    }
    if (half) {
        #pragma unroll
        for (int c = 0; c < NCLS; c++) lghf[r * NCLS + c] = lg[c];
    }
    __syncthreads();

    if (!half) {
        #pragma unroll
        for (int c = 0; c < NCLS; c++) lg[c] += lghf[r * NCLS + c];
        float* dst = &g_lg_part[((size_t)tileN * B_ROWS + bm + r) * NCLS];
        #pragma unroll
        for (int c = 0; c < NCLS; c++) dst[c] = lg[c];
    } else {
        int f0 = bn / POOLK;
        int f1 = (bn + 127) / POOLK; if (f1 > NF - 1) f1 = NF - 1;
        for (int f = f0; f <= f1; f++) {
            int c0 = POOLK * f - bn, c1 = c0 + POOLK - 1;
            if (c0 < 0) c0 = 0;
            if (c1 > 127) c1 = 127;
            float sum = 0.f;
            for (int c = c0; c <= c1; c++) sum += stg[c * STG_STRIDE + r];
            int slot = (tileN == (POOLK * f) >> 7) ? 0 : 1;
            g_pool_part[((size_t)f * 2 + slot) * B_ROWS + bm + r] = sum;
        }
    }
}

// ------------------------------------------------------------------
// Kernel 2: per-feature inclusive scan of (v, v^2) over batch (coalesced)
// ------------------------------------------------------------------
__global__ __launch_bounds__(256) void scan_kernel()
{
    const int f = blockIdx.x;
    const int t = threadIdx.x, lane = t & 31, w = t >> 5;
    const bool two = ((POOLK * f) >> 7) != ((POOLK * f + POOLK - 1) >> 7);
    const float* P0 = &g_pool_part[(size_t)f * 2 * B_ROWS];
    const float* P1 = P0 + B_ROWS;
    __shared__ float2 wtot[8];
    float2 carry = make_float2(0.f, 0.f);

    for (int chunk = 0; chunk < B_ROWS / 256; chunk++) {
        int i = chunk * 256 + t;
        float v = P0[i];
        if (two) v += P1[i];
        v *= (1.0f / (float)POOLK);
        float2 s = make_float2(v, v * v);
        #pragma unroll
        for (int off = 1; off < 32; off <<= 1) {
            float a  = __shfl_up_sync(0xffffffffu, s.x, off);
            float b2 = __shfl_up_sync(0xffffffffu, s.y, off);
            if (lane >= off) { s.x += a; s.y += b2; }
        }
        if (lane == 31) wtot[w] = s;
        __syncthreads();
        if (w == 0 && lane < 8) {
            float2 xx = wtot[lane];
            #pragma unroll
            for (int off = 1; off < 8; off <<= 1) {
                float a  = __shfl_up_sync(0xffu, xx.x, off);
                float b2 = __shfl_up_sync(0xffu, xx.y, off);
                if (lane >= off) { xx.x += a; xx.y += b2; }
            }
            wtot[lane] = xx;
        }
        __syncthreads();
        float2 pre = carry;
        if (w > 0) { pre.x += wtot[w - 1].x; pre.y += wtot[w - 1].y; }
        g_cs[i * NF + f] = make_float2(s.x + pre.x, s.y + pre.y);
        carry.x += wtot[7].x;
        carry.y += wtot[7].y;
        __syncthreads();
    }
}

// ------------------------------------------------------------------
// Kernel 3: final — warp per row: sum tile partials + est·WlE + softmax
// ------------------------------------------------------------------
__global__ __launch_bounds__(256) void final_kernel(
    const float* __restrict__ b_lin, float* __restrict__ out)
{
    const int t = threadIdx.x, lane = t & 31, wid = t >> 5;
    __shared__ float est_s[8][272];

    for (int e = t; e < 8 * ESTD; e += 256) {
        int r = e / ESTD, e2 = e % ESTD;
        int f = e2 / 6, rem = e2 % 6, j = rem >> 1, sflag = rem & 1;
        int L = (j == 0) ? 32 : (j == 1) ? 128 : 512;
        int bb = blockIdx.x * 8 + r;
        float2 c1 = g_cs[bb * NF + f];
        float2 c0 = (bb >= L) ? g_cs[(bb - L) * NF + f] : make_float2(0.f, 0.f);
        float cnt = fminf((float)(bb + 1), (float)L);
        float m = (c1.x - c0.x) / cnt;
        est_s[r][e2] = (sflag == 0) ? m : ((c1.y - c0.y) / cnt - m * m);
    }
    __syncthreads();

    const int row = blockIdx.x * 8 + wid;

    float acc[NCLS];
    #pragma unroll
    for (int c = 0; c < NCLS; c++) acc[c] = 0.f;

    if (lane < NTILE) {
        const float* p = &g_lg_part[((size_t)lane * B_ROWS + row) * NCLS];
        #pragma unroll
        for (int c = 0; c < NCLS; c++) acc[c] += p[c];
    }
    for (int e = lane; e < ESTD; e += 32) {
        float ev = est_s[wid][e];
        #pragma unroll
        for (int c = 0; c < NCLS; c++) acc[c] += ev * g_WlE[c * 288 + e];
    }
    #pragma unroll
    for (int c = 0; c < NCLS; c++) {
        #pragma unroll
        for (int off = 16; off > 0; off >>= 1)
            acc[c] += __shfl_down_sync(0xffffffffu, acc[c], off);
    }
    if (lane == 0) {
        float lg[NCLS], mx = -1e30f;
        #pragma unroll
        for (int c = 0; c < NCLS; c++) { lg[c] = acc[c] + b_lin[c]; mx = fmaxf(mx, lg[c]); }
        float sum = 0.f;
        #pragma unroll
        for (int c = 0; c < NCLS; c++) { lg[c] = expf(lg[c] - mx); sum += lg[c]; }
        float inv = 1.0f / sum;
        #pragma unroll
        for (int c = 0; c < NCLS; c++) out[row * NCLS + c] = lg[c] * inv;
    }
}

// ------------------------------------------------------------------
extern "C" void kernel_launch(void* const* d_in, const int* in_sizes, int n_in,
                              void* d_out, int out_size)
{
    (void)in_sizes; (void)n_in; (void)out_size;
    const float* x     = (const float*)d_in[0];
    const float* W_ih  = (const float*)d_in[1];
    // d_in[2] = W_hh — dead: seq_len==1 and h0==0
    const float* b_ih  = (const float*)d_in[3];
    const float* b_hh  = (const float*)d_in[4];
    const float* W_lin = (const float*)d_in[5];
    const float* b_lin = (const float*)d_in[6];
    float* out = (float*)d_out;

    cudaFuncSetAttribute(gemm_tanh_kernel,
                         cudaFuncAttributeMaxDynamicSharedMemorySize, GEMM_SMEM_BYTES);

    __nv_bfloat16 *xb, *wb;
    cudaGetSymbolAddress((void**)&xb, g_xb);
    cudaGetSymbolAddress((void**)&wb, g_wb);

    int nx4 = (B_ROWS * INP) / 4;
    int nw4 = (HID * INP) / 4;

    // GEMM kept as 4th launch (ncu capture slot)
    cvt_bf16_kernel<<<(nx4 + 255) / 256, 256>>>(x, xb, nx4);
    cvt_bf16_kernel<<<(nw4 + 255) / 256, 256>>>(W_ih, wb, nw4);
    prep_wl_kernel<<<(PREP_N + 255) / 256, 256>>>(W_lin);

    dim3 g1(HID / BN, B_ROWS / BM);   // 16 x 64 = 1024 CTAs, 2 per SM
    gemm_tanh_kernel<<<g1, NTHREADS, GEMM_SMEM_BYTES>>>(b_ih, b_hh);

    scan_kernel<<<NF, 256>>>();
    final_kernel<<<B_ROWS / 8, 256>>>(b_lin, out);
}

// round 13
// speedup vs baseline: 1.9211x; 1.0086x over previous
#include <cuda_runtime.h>
#include <cuda_bf16.h>
#include <cstdint>
#include <math.h>

#define B_ROWS 8192
#define HID    2048
#define INP    2048
#define NCLS   10
#define POOLK  45
#define NF     45
#define ESTD   270
#define WLD    2318   // W_lin leading dim (HID + ESTD)
#define NTILE  (HID / 128)   // 16 N-tiles

// ---- GEMM tiling: bf16 m16n8k16, CTA 128x128, 4 warps, warp tile 64x64 ----
#define BM 128
#define BN 128
#define BKS 64               // K (bf16 elems) per stage
#define NSTG_IT (INP / BKS)  // 32 stage iterations
#define LDKB 72              // padded bf16 per smem row (144 B)
#define SA_BYTES (BM * LDKB * 2)       // 18432
#define STAGE_BYTES (2 * SA_BYTES)     // 36864 (A + B)
#define NSTAGE 2
#define GEMM_SMEM_BYTES (NSTAGE * STAGE_BYTES)   // 73728 -> 3 CTAs/SM
#define NTHREADS 128          // 4 warps: 2M x 2N, warp tile 64x64

// epilogue smem overlay (floats, within dsm): 64-col staging + W_lin slice
#define STG_STRIDE 132
#define SWL_OFF (64 * STG_STRIDE)      // 8448
// total 8448 + 1280 = 9728 floats = 38.9 KB <= 73.7 KB ✓

// Scratch (device globals — no runtime allocation)
__device__ __nv_bfloat16 g_xb[(size_t)B_ROWS * INP];
__device__ __nv_bfloat16 g_wb[(size_t)HID * INP];
__device__ float  g_Wl[NCLS * HID];
__device__ float  g_WlE[NCLS * 288];
__device__ float  g_lg_part[(size_t)NTILE * B_ROWS * NCLS];
__device__ float  g_pool_part[(size_t)NF * 2 * B_ROWS];
__device__ float2 g_cs[B_ROWS * NF];

// ------------------------------------------------------------------
__device__ __forceinline__ uint32_t smem_u32(const void* p) {
    return (uint32_t)__cvta_generic_to_shared(p);
}
__device__ __forceinline__ void cp16(uint32_t dst, const void* src) {
    asm volatile("cp.async.cg.shared.global [%0], [%1], 16;\n" :: "r"(dst), "l"(src));
}
__device__ __forceinline__ void ldsm_x4(uint32_t& r0, uint32_t& r1, uint32_t& r2,
                                        uint32_t& r3, uint32_t addr) {
    asm volatile("ldmatrix.sync.aligned.m8n8.x4.shared.b16 {%0,%1,%2,%3}, [%4];"
                 : "=r"(r0), "=r"(r1), "=r"(r2), "=r"(r3) : "r"(addr));
}
__device__ __forceinline__ void mma_bf16(float* d, const uint32_t* a,
                                         uint32_t b0, uint32_t b1) {
    asm volatile(
        "mma.sync.aligned.m16n8k16.row.col.f32.bf16.bf16.f32 "
        "{%0,%1,%2,%3}, {%4,%5,%6,%7}, {%8,%9}, {%0,%1,%2,%3};"
        : "+f"(d[0]), "+f"(d[1]), "+f"(d[2]), "+f"(d[3])
        : "r"(a[0]), "r"(a[1]), "r"(a[2]), "r"(a[3]), "r"(b0), "r"(b1));
}
__device__ __forceinline__ float tanh_fast(float x) {
    float r;
    asm("tanh.approx.f32 %0, %1;" : "=f"(r) : "f"(x));
    return r;
}

// ------------------------------------------------------------------
// Kernel 0a: fp32 -> bf16 (round-to-nearest)
// ------------------------------------------------------------------
__global__ __launch_bounds__(256) void cvt_bf16_kernel(
    const float* __restrict__ src, __nv_bfloat16* __restrict__ dst, int n4)
{
    int i = blockIdx.x * 256 + threadIdx.x;
    if (i >= n4) return;
    float4 v = ((const float4*)src)[i];
    __nv_bfloat162* d2 = (__nv_bfloat162*)dst;
    d2[2 * i]     = __floats2bfloat162_rn(v.x, v.y);
    d2[2 * i + 1] = __floats2bfloat162_rn(v.z, v.w);
}

// ------------------------------------------------------------------
// Kernel 0b: pack W_lin into aligned buffers
// ------------------------------------------------------------------
#define PREP_N (NCLS * HID + NCLS * ESTD)
__global__ __launch_bounds__(256) void prep_wl_kernel(const float* __restrict__ Wl)
{
    int idx = blockIdx.x * 256 + threadIdx.x;
    if (idx >= PREP_N) return;
    int n1 = NCLS * HID;
    if (idx < n1) {
        int c = idx / HID, k = idx % HID;
        g_Wl[idx] = Wl[(size_t)c * WLD + k];
    } else {
        int j = idx - n1;
        int c = j / ESTD, e = j % ESTD;
        g_WlE[c * 288 + e] = Wl[(size_t)c * WLD + HID + e];
    }
}

// ------------------------------------------------------------------
// Kernel 1: GEMM(bf16) + tanh + fused pool/logits partials
// 4 warps, warp tile 64x64, 2-stage cp.async, 3 CTAs/SM
// ------------------------------------------------------------------
__device__ __forceinline__ void load_stage(char* sbase, int bm, int bn, int kt, int tid)
{
    uint32_t su = smem_u32(sbase);
    #pragma unroll
    for (int i = 0; i < 8; i++) {
        int ci = tid + i * NTHREADS;
        int r = ci >> 3, ko = (ci & 7) << 3;
        cp16(su + (uint32_t)(r * LDKB + ko) * 2,
             g_xb + (size_t)(bm + r) * INP + kt + ko);
    }
    uint32_t sub = su + SA_BYTES;
    #pragma unroll
    for (int i = 0; i < 8; i++) {
        int ci = tid + i * NTHREADS;
        int r = ci >> 3, ko = (ci & 7) << 3;
        cp16(sub + (uint32_t)(r * LDKB + ko) * 2,
             g_wb + (size_t)(bn + r) * INP + kt + ko);
    }
    asm volatile("cp.async.commit_group;" ::: "memory");
}

__global__ __launch_bounds__(NTHREADS, 3) void gemm_tanh_kernel(
    const float* __restrict__ b_ih, const float* __restrict__ b_hh)
{
    extern __shared__ char dsmc[];
    float* dsm = (float*)dsmc;
    __shared__ float sbias[BN];

    const int tid  = threadIdx.x;
    const int warp = tid >> 5;
    const int lane = tid & 31;
    const int qid  = lane >> 2;
    const int tq   = lane & 3;
    const int bm = blockIdx.y * BM;
    const int bn = blockIdx.x * BN;

    if (tid < BN) sbias[tid] = b_ih[bn + tid] + b_hh[bn + tid];

    const int wm = (warp & 1) * 64;    // 2 warps along M
    const int wn = (warp >> 1) * 64;   // 2 warps along N

    const int arow = lane & 15;
    const int akof = (lane >> 4) * 8;

    float acc[4][8][4];
    #pragma unroll
    for (int mf = 0; mf < 4; mf++)
        #pragma unroll
        for (int nf = 0; nf < 8; nf++)
            #pragma unroll
            for (int e = 0; e < 4; e++) acc[mf][nf][e] = 0.f;

    load_stage(dsmc,               bm, bn, 0,   tid);
    load_stage(dsmc + STAGE_BYTES, bm, bn, BKS, tid);

    for (int s = 0; s < NSTG_IT; s++) {
        if (s >= NSTG_IT - 1)
            asm volatile("cp.async.wait_group 0;" ::: "memory");
        else
            asm volatile("cp.async.wait_group 1;" ::: "memory");
        __syncthreads();

        char* sA = dsmc + (s & 1) * STAGE_BYTES;
        uint32_t sAu = smem_u32(sA);
        const uint32_t* sB = (const uint32_t*)(sA + SA_BYTES);

        #pragma unroll
        for (int kk = 0; kk < BKS; kk += 16) {
            uint32_t b[8][2];
            #pragma unroll
            for (int nf = 0; nf < 8; nf++) {
                int roww = (wn + nf * 8 + qid) * (LDKB / 2) + (kk >> 1) + tq;
                b[nf][0] = sB[roww];
                b[nf][1] = sB[roww + 4];
            }
            #pragma unroll
            for (int mf = 0; mf < 4; mf++) {
                uint32_t a[4];
                uint32_t addr = sAu +
                    (uint32_t)((wm + mf * 16 + arow) * LDKB + kk + akof) * 2;
                ldsm_x4(a[0], a[1], a[2], a[3], addr);
                #pragma unroll
                for (int nf = 0; nf < 8; nf++)
                    mma_bf16(acc[mf][nf], a, b[nf][0], b[nf][1]);
            }
        }

        // prefetch stage s+2 into the buffer just freed
        if (s + 2 < NSTG_IT) {
            __syncthreads();
            load_stage(dsmc + (s & 1) * STAGE_BYTES, bm, bn, (s + 2) * BKS, tid);
        }
    }

    // ---------- fused epilogue: two 64-column passes ----------
    float* stg = dsm;               // 64 x 132 transposed staging
    float* sWl = dsm + SWL_OFF;     // [class][128]

    __syncthreads();
    for (int i = tid; i < NCLS * 128; i += NTHREADS)
        sWl[i] = g_Wl[(i >> 7) * HID + bn + (i & 127)];

    const int r = tid;              // row 0..127
    const int tileN = bn >> 7;
    int f0 = bn / POOLK;
    int f1 = (bn + 127) / POOLK; if (f1 > NF - 1) f1 = NF - 1;

    float lg[NCLS];
    #pragma unroll
    for (int c = 0; c < NCLS; c++) lg[c] = 0.f;
    float fsum[4] = {0.f, 0.f, 0.f, 0.f};

    for (int pass = 0; pass < 2; pass++) {
        __syncthreads();   // stg free for reuse
        if ((warp >> 1) == pass) {
            #pragma unroll
            for (int mf = 0; mf < 4; mf++) {
                int r0 = wm + mf * 16 + qid;
                #pragma unroll
                for (int nf = 0; nf < 8; nf++) {
                    int lc = nf * 8 + tq * 2;        // local col within pass
                    int gc = wn + lc;                // global col in tile
                    float b0 = sbias[gc], b1 = sbias[gc + 1];
                    stg[lc * STG_STRIDE + r0]           = tanh_fast(acc[mf][nf][0] + b0);
                    stg[(lc + 1) * STG_STRIDE + r0]     = tanh_fast(acc[mf][nf][1] + b1);
                    stg[lc * STG_STRIDE + r0 + 8]       = tanh_fast(acc[mf][nf][2] + b0);
                    stg[(lc + 1) * STG_STRIDE + r0 + 8] = tanh_fast(acc[mf][nf][3] + b1);
                }
            }
        }
        __syncthreads();

        const int cbase = pass * 64;
        #pragma unroll 4
        for (int j = 0; j < 64; j++) {
            float y = stg[j * STG_STRIDE + r];
            #pragma unroll
            for (int c = 0; c < NCLS; c++) lg[c] += y * sWl[c * 128 + cbase + j];
        }
        for (int fi = 0; fi <= f1 - f0; fi++) {
            int f = f0 + fi;
            int c0 = POOLK * f - bn, c1 = c0 + POOLK - 1;
            if (c0 < cbase) c0 = cbase;
            if (c1 > cbase + 63) c1 = cbase + 63;
            float sum = 0.f;
            for (int c = c0; c <= c1; c++) sum += stg[(c - cbase) * STG_STRIDE + r];
            fsum[fi] += sum;
        }
    }

    float* dst = &g_lg_part[((size_t)tileN * B_ROWS + bm + r) * NCLS];
    #pragma unroll
    for (int c = 0; c < NCLS; c++) dst[c] = lg[c];
    for (int fi = 0; fi <= f1 - f0; fi++) {
        int f = f0 + fi;
        int c0 = POOLK * f - bn;
        int c1 = c0 + POOLK - 1;
        if (c0 < 0 || c1 > 127) {
            // partial window in this tile -> slot by which tile owns its start
            int slot = (tileN == (POOLK * f) >> 7) ? 0 : 1;
            g_pool_part[((size_t)f * 2 + slot) * B_ROWS + bm + r] = fsum[fi];
        } else {
            // fully inside: slot 0 (scan adds slot1 only when window spans tiles)
            g_pool_part[((size_t)f * 2 + 0) * B_ROWS + bm + r] = fsum[fi];
        }
    }
}

// ------------------------------------------------------------------
// Kernel 2: per-feature inclusive scan of (v, v^2) over batch (coalesced)
// ------------------------------------------------------------------
__global__ __launch_bounds__(256) void scan_kernel()
{
    const int f = blockIdx.x;
    const int t = threadIdx.x, lane = t & 31, w = t >> 5;
    const bool two = ((POOLK * f) >> 7) != ((POOLK * f + POOLK - 1) >> 7);
    const float* P0 = &g_pool_part[(size_t)f * 2 * B_ROWS];
    const float* P1 = P0 + B_ROWS;
    __shared__ float2 wtot[8];
    float2 carry = make_float2(0.f, 0.f);

    for (int chunk = 0; chunk < B_ROWS / 256; chunk++) {
        int i = chunk * 256 + t;
        float v = P0[i];
        if (two) v += P1[i];
        v *= (1.0f / (float)POOLK);
        float2 s = make_float2(v, v * v);
        #pragma unroll
        for (int off = 1; off < 32; off <<= 1) {
            float a  = __shfl_up_sync(0xffffffffu, s.x, off);
            float b2 = __shfl_up_sync(0xffffffffu, s.y, off);
            if (lane >= off) { s.x += a; s.y += b2; }
        }
        if (lane == 31) wtot[w] = s;
        __syncthreads();
        if (w == 0 && lane < 8) {
            float2 xx = wtot[lane];
            #pragma unroll
            for (int off = 1; off < 8; off <<= 1) {
                float a  = __shfl_up_sync(0xffu, xx.x, off);
                float b2 = __shfl_up_sync(0xffu, xx.y, off);
                if (lane >= off) { xx.x += a; xx.y += b2; }
            }
            wtot[lane] = xx;
        }
        __syncthreads();
        float2 pre = carry;
        if (w > 0) { pre.x += wtot[w - 1].x; pre.y += wtot[w - 1].y; }
        g_cs[i * NF + f] = make_float2(s.x + pre.x, s.y + pre.y);
        carry.x += wtot[7].x;
        carry.y += wtot[7].y;
        __syncthreads();
    }
}

// ------------------------------------------------------------------
// Kernel 3: final — warp per row: sum tile partials + est·WlE + softmax
// ------------------------------------------------------------------
__global__ __launch_bounds__(256) void final_kernel(
    const float* __restrict__ b_lin, float* __restrict__ out)
{
    const int t = threadIdx.x, lane = t & 31, wid = t >> 5;
    __shared__ float est_s[8][272];

    for (int e = t; e < 8 * ESTD; e += 256) {
        int r = e / ESTD, e2 = e % ESTD;
        int f = e2 / 6, rem = e2 % 6, j = rem >> 1, sflag = rem & 1;
        int L = (j == 0) ? 32 : (j == 1) ? 128 : 512;
        int bb = blockIdx.x * 8 + r;
        float2 c1 = g_cs[bb * NF + f];
        float2 c0 = (bb >= L) ? g_cs[(bb - L) * NF + f] : make_float2(0.f, 0.f);
        float cnt = fminf((float)(bb + 1), (float)L);
        float m = (c1.x - c0.x) / cnt;
        est_s[r][e2] = (sflag == 0) ? m : ((c1.y - c0.y) / cnt - m * m);
    }
    __syncthreads();

    const int row = blockIdx.x * 8 + wid;

    float acc[NCLS];
    #pragma unroll
    for (int c = 0; c < NCLS; c++) acc[c] = 0.f;

    if (lane < NTILE) {
        const float* p = &g_lg_part[((size_t)lane * B_ROWS + row) * NCLS];
        #pragma unroll
        for (int c = 0; c < NCLS; c++) acc[c] += p[c];
    }
    for (int e = lane; e < ESTD; e += 32) {
        float ev = est_s[wid][e];
        #pragma unroll
        for (int c = 0; c < NCLS; c++) acc[c] += ev * g_WlE[c * 288 + e];
    }
    #pragma unroll
    for (int c = 0; c < NCLS; c++) {
        #pragma unroll
        for (int off = 16; off > 0; off >>= 1)
            acc[c] += __shfl_down_sync(0xffffffffu, acc[c], off);
    }
    if (lane == 0) {
        float lg[NCLS], mx = -1e30f;
        #pragma unroll
        for (int c = 0; c < NCLS; c++) { lg[c] = acc[c] + b_lin[c]; mx = fmaxf(mx, lg[c]); }
        float sum = 0.f;
        #pragma unroll
        for (int c = 0; c < NCLS; c++) { lg[c] = expf(lg[c] - mx); sum += lg[c]; }
        float inv = 1.0f / sum;
        #pragma unroll
        for (int c = 0; c < NCLS; c++) out[row * NCLS + c] = lg[c] * inv;
    }
}

// ------------------------------------------------------------------
extern "C" void kernel_launch(void* const* d_in, const int* in_sizes, int n_in,
                              void* d_out, int out_size)
{
    (void)in_sizes; (void)n_in; (void)out_size;
    const float* x     = (const float*)d_in[0];
    const float* W_ih  = (const float*)d_in[1];
    // d_in[2] = W_hh — dead: seq_len==1 and h0==0
    const float* b_ih  = (const float*)d_in[3];
    const float* b_hh  = (const float*)d_in[4];
    const float* W_lin = (const float*)d_in[5];
    const float* b_lin = (const float*)d_in[6];
    float* out = (float*)d_out;

    cudaFuncSetAttribute(gemm_tanh_kernel,
                         cudaFuncAttributeMaxDynamicSharedMemorySize, GEMM_SMEM_BYTES);

    __nv_bfloat16 *xb, *wb;
    cudaGetSymbolAddress((void**)&xb, g_xb);
    cudaGetSymbolAddress((void**)&wb, g_wb);

    int nx4 = (B_ROWS * INP) / 4;
    int nw4 = (HID * INP) / 4;

    // GEMM kept as 4th launch (ncu capture slot)
    cvt_bf16_kernel<<<(nx4 + 255) / 256, 256>>>(x, xb, nx4);
    cvt_bf16_kernel<<<(nw4 + 255) / 256, 256>>>(W_ih, wb, nw4);
    prep_wl_kernel<<<(PREP_N + 255) / 256, 256>>>(W_lin);

    dim3 g1(HID / BN, B_ROWS / BM);   // 16 x 64 = 1024 CTAs, 3 per SM
    gemm_tanh_kernel<<<g1, NTHREADS, GEMM_SMEM_BYTES>>>(b_ih, b_hh);

    scan_kernel<<<NF, 256>>>();
    final_kernel<<<B_ROWS / 8, 256>>>(b_lin, out);
}

// round 14
// speedup vs baseline: 2.0056x; 1.0440x over previous
#include <cuda_runtime.h>
#include <cuda_bf16.h>
#include <cstdint>
#include <math.h>

#define B_ROWS 8192
#define HID    2048
#define INP    2048
#define NCLS   10
#define POOLK  45
#define NF     45
#define ESTD   270
#define WLD    2318   // W_lin leading dim (HID + ESTD)
#define NTILE  (HID / 128)   // 16 N-tiles

// ---- GEMM tiling: bf16 m16n8k16, CTA 128x128, 4 warps, warp tile 64x64 ----
#define BM 128
#define BN 128
#define BKS 64               // K (bf16 elems) per stage
#define NSTG_IT (INP / BKS)  // 32 stage iterations
#define LDKB 72              // padded bf16 per smem row (144 B)
#define SA_BYTES (BM * LDKB * 2)       // 18432
#define STAGE_BYTES (2 * SA_BYTES)     // 36864 (A + B)
#define NSTAGE 2
#define GEMM_SMEM_BYTES (NSTAGE * STAGE_BYTES)   // 73728 -> 3 CTAs/SM
#define NTHREADS 128          // 4 warps: 2M x 2N, warp tile 64x64

// epilogue smem overlay (floats, within dsm)
#define STG_STRIDE 132
#define SWL_OFF (64 * STG_STRIDE)

// Scratch (device globals — no runtime allocation)
__device__ __nv_bfloat16 g_xb[(size_t)B_ROWS * INP];
__device__ __nv_bfloat16 g_wb[(size_t)HID * INP];
__device__ float  g_Wl[NCLS * HID];
__device__ float  g_WlE[NCLS * 288];
__device__ float  g_lg_part[(size_t)NTILE * B_ROWS * NCLS];
__device__ float  g_pool_part[(size_t)NF * 2 * B_ROWS];
__device__ float2 g_cs[B_ROWS * NF];

// ------------------------------------------------------------------
__device__ __forceinline__ uint32_t smem_u32(const void* p) {
    return (uint32_t)__cvta_generic_to_shared(p);
}
__device__ __forceinline__ void cp16(uint32_t dst, const void* src) {
    asm volatile("cp.async.cg.shared.global [%0], [%1], 16;\n" :: "r"(dst), "l"(src));
}
__device__ __forceinline__ void ldsm_x4(uint32_t& r0, uint32_t& r1, uint32_t& r2,
                                        uint32_t& r3, uint32_t addr) {
    asm volatile("ldmatrix.sync.aligned.m8n8.x4.shared.b16 {%0,%1,%2,%3}, [%4];"
                 : "=r"(r0), "=r"(r1), "=r"(r2), "=r"(r3) : "r"(addr));
}
__device__ __forceinline__ void mma_bf16(float* d, const uint32_t* a,
                                         uint32_t b0, uint32_t b1) {
    asm volatile(
        "mma.sync.aligned.m16n8k16.row.col.f32.bf16.bf16.f32 "
        "{%0,%1,%2,%3}, {%4,%5,%6,%7}, {%8,%9}, {%0,%1,%2,%3};"
        : "+f"(d[0]), "+f"(d[1]), "+f"(d[2]), "+f"(d[3])
        : "r"(a[0]), "r"(a[1]), "r"(a[2]), "r"(a[3]), "r"(b0), "r"(b1));
}
__device__ __forceinline__ float tanh_fast(float x) {
    float r;
    asm("tanh.approx.f32 %0, %1;" : "=f"(r) : "f"(x));
    return r;
}

// ------------------------------------------------------------------
// Kernel 0a: fp32 -> bf16 (round-to-nearest)
// ------------------------------------------------------------------
__global__ __launch_bounds__(256) void cvt_bf16_kernel(
    const float* __restrict__ src, __nv_bfloat16* __restrict__ dst, int n4)
{
    int i = blockIdx.x * 256 + threadIdx.x;
    if (i >= n4) return;
    float4 v = ((const float4*)src)[i];
    __nv_bfloat162* d2 = (__nv_bfloat162*)dst;
    d2[2 * i]     = __floats2bfloat162_rn(v.x, v.y);
    d2[2 * i + 1] = __floats2bfloat162_rn(v.z, v.w);
}

// ------------------------------------------------------------------
// Kernel 0b: pack W_lin into aligned buffers
// ------------------------------------------------------------------
#define PREP_N (NCLS * HID + NCLS * ESTD)
__global__ __launch_bounds__(256) void prep_wl_kernel(const float* __restrict__ Wl)
{
    int idx = blockIdx.x * 256 + threadIdx.x;
    if (idx >= PREP_N) return;
    int n1 = NCLS * HID;
    if (idx < n1) {
        int c = idx / HID, k = idx % HID;
        g_Wl[idx] = Wl[(size_t)c * WLD + k];
    } else {
        int j = idx - n1;
        int c = j / ESTD, e = j % ESTD;
        g_WlE[c * 288 + e] = Wl[(size_t)c * WLD + HID + e];
    }
}

// ------------------------------------------------------------------
// Kernel 1: GEMM(bf16) + tanh + fused pool/logits partials
// 4 warps, warp tile 64x64, 2-stage cp.async, 3 CTAs/SM,
// BOTH operands via natural bf16 ldmatrix
// ------------------------------------------------------------------
__device__ __forceinline__ void load_stage(char* sbase, int bm, int bn, int kt, int tid)
{
    uint32_t su = smem_u32(sbase);
    #pragma unroll
    for (int i = 0; i < 8; i++) {
        int ci = tid + i * NTHREADS;
        int r = ci >> 3, ko = (ci & 7) << 3;
        cp16(su + (uint32_t)(r * LDKB + ko) * 2,
             g_xb + (size_t)(bm + r) * INP + kt + ko);
    }
    uint32_t sub = su + SA_BYTES;
    #pragma unroll
    for (int i = 0; i < 8; i++) {
        int ci = tid + i * NTHREADS;
        int r = ci >> 3, ko = (ci & 7) << 3;
        cp16(sub + (uint32_t)(r * LDKB + ko) * 2,
             g_wb + (size_t)(bn + r) * INP + kt + ko);
    }
    asm volatile("cp.async.commit_group;" ::: "memory");
}

__global__ __launch_bounds__(NTHREADS, 3) void gemm_tanh_kernel(
    const float* __restrict__ b_ih, const float* __restrict__ b_hh)
{
    extern __shared__ char dsmc[];
    float* dsm = (float*)dsmc;
    __shared__ float sbias[BN];

    const int tid  = threadIdx.x;
    const int warp = tid >> 5;
    const int lane = tid & 31;
    const int qid  = lane >> 2;
    const int tq   = lane & 3;
    const int bm = blockIdx.y * BM;
    const int bn = blockIdx.x * BN;

    if (tid < BN) sbias[tid] = b_ih[bn + tid] + b_hh[bn + tid];

    const int wm = (warp & 1) * 64;    // 2 warps along M
    const int wn = (warp >> 1) * 64;   // 2 warps along N

    // A ldmatrix selectors: lane -> row (l&15), k-half (l>>4)*8 (bf16 elems)
    const uint32_t aoff = (uint32_t)((lane & 15) * LDKB + (lane >> 4) * 8) * 2;
    // B ldmatrix per-lane offset (bytes): matrices = (n-half, k-half) pairs
    //   row n = (lane>>4)*8 + (lane&7), k-word shift = ((lane>>3)&1)*16 bytes
    const uint32_t boff = (uint32_t)((wn + ((lane >> 4) & 1) * 8 + (lane & 7)) * LDKB) * 2
                        + ((lane >> 3) & 1) * 16;

    float acc[4][8][4];
    #pragma unroll
    for (int mf = 0; mf < 4; mf++)
        #pragma unroll
        for (int nf = 0; nf < 8; nf++)
            #pragma unroll
            for (int e = 0; e < 4; e++) acc[mf][nf][e] = 0.f;

    load_stage(dsmc,               bm, bn, 0,   tid);
    load_stage(dsmc + STAGE_BYTES, bm, bn, BKS, tid);

    for (int s = 0; s < NSTG_IT; s++) {
        if (s >= NSTG_IT - 1)
            asm volatile("cp.async.wait_group 0;" ::: "memory");
        else
            asm volatile("cp.async.wait_group 1;" ::: "memory");
        __syncthreads();

        char* sA = dsmc + (s & 1) * STAGE_BYTES;
        uint32_t sAu = smem_u32(sA);
        uint32_t sBu = sAu + SA_BYTES;

        #pragma unroll
        for (int kk = 0; kk < BKS; kk += 16) {
            uint32_t b[8][2];
            #pragma unroll
            for (int p = 0; p < 4; p++) {   // nf pair p -> tiles 2p, 2p+1
                uint32_t addr = sBu + boff + (uint32_t)(p * 16 * LDKB * 2) + kk * 2;
                ldsm_x4(b[2 * p][0], b[2 * p][1], b[2 * p + 1][0], b[2 * p + 1][1], addr);
            }
            #pragma unroll
            for (int mf = 0; mf < 4; mf++) {
                uint32_t a[4];
                uint32_t addr = sAu + aoff +
                    (uint32_t)((wm + mf * 16) * LDKB + kk) * 2;
                ldsm_x4(a[0], a[1], a[2], a[3], addr);
                #pragma unroll
                for (int nf = 0; nf < 8; nf++)
                    mma_bf16(acc[mf][nf], a, b[nf][0], b[nf][1]);
            }
        }

        // prefetch stage s+2 into the buffer just freed
        if (s + 2 < NSTG_IT) {
            __syncthreads();
            load_stage(dsmc + (s & 1) * STAGE_BYTES, bm, bn, (s + 2) * BKS, tid);
        }
    }

    // ---------- fused epilogue: two 64-column passes ----------
    float* stg = dsm;
    float* sWl = dsm + SWL_OFF;

    __syncthreads();
    for (int i = tid; i < NCLS * 128; i += NTHREADS)
        sWl[i] = g_Wl[(i >> 7) * HID + bn + (i & 127)];

    const int r = tid;
    const int tileN = bn >> 7;
    int f0 = bn / POOLK;
    int f1 = (bn + 127) / POOLK; if (f1 > NF - 1) f1 = NF - 1;

    float lg[NCLS];
    #pragma unroll
    for (int c = 0; c < NCLS; c++) lg[c] = 0.f;
    float fsum[4] = {0.f, 0.f, 0.f, 0.f};

    for (int pass = 0; pass < 2; pass++) {
        __syncthreads();
        if ((warp >> 1) == pass) {
            #pragma unroll
            for (int mf = 0; mf < 4; mf++) {
                int r0 = wm + mf * 16 + qid;
                #pragma unroll
                for (int nf = 0; nf < 8; nf++) {
                    int lc = nf * 8 + tq * 2;
                    int gc = wn + lc;
                    float b0 = sbias[gc], b1 = sbias[gc + 1];
                    stg[lc * STG_STRIDE + r0]           = tanh_fast(acc[mf][nf][0] + b0);
                    stg[(lc + 1) * STG_STRIDE + r0]     = tanh_fast(acc[mf][nf][1] + b1);
                    stg[lc * STG_STRIDE + r0 + 8]       = tanh_fast(acc[mf][nf][2] + b0);
                    stg[(lc + 1) * STG_STRIDE + r0 + 8] = tanh_fast(acc[mf][nf][3] + b1);
                }
            }
        }
        __syncthreads();

        const int cbase = pass * 64;
        #pragma unroll 4
        for (int j = 0; j < 64; j++) {
            float y = stg[j * STG_STRIDE + r];
            #pragma unroll
            for (int c = 0; c < NCLS; c++) lg[c] += y * sWl[c * 128 + cbase + j];
        }
        for (int fi = 0; fi <= f1 - f0; fi++) {
            int f = f0 + fi;
            int c0 = POOLK * f - bn, c1 = c0 + POOLK - 1;
            if (c0 < cbase) c0 = cbase;
            if (c1 > cbase + 63) c1 = cbase + 63;
            float sum = 0.f;
            for (int c = c0; c <= c1; c++) sum += stg[(c - cbase) * STG_STRIDE + r];
            fsum[fi] += sum;
        }
    }

    float* dst = &g_lg_part[((size_t)tileN * B_ROWS + bm + r) * NCLS];
    #pragma unroll
    for (int c = 0; c < NCLS; c++) dst[c] = lg[c];
    for (int fi = 0; fi <= f1 - f0; fi++) {
        int f = f0 + fi;
        int c0 = POOLK * f - bn;
        int c1 = c0 + POOLK - 1;
        if (c0 < 0 || c1 > 127) {
            int slot = (tileN == (POOLK * f) >> 7) ? 0 : 1;
            g_pool_part[((size_t)f * 2 + slot) * B_ROWS + bm + r] = fsum[fi];
        } else {
            g_pool_part[((size_t)f * 2 + 0) * B_ROWS + bm + r] = fsum[fi];
        }
    }
}

// ------------------------------------------------------------------
// Kernel 2: per-feature inclusive scan, 1024 threads (8 chunks)
// ------------------------------------------------------------------
#define SCT 1024
__global__ __launch_bounds__(SCT) void scan_kernel()
{
    const int f = blockIdx.x;
    const int t = threadIdx.x, lane = t & 31, w = t >> 5;   // 32 warps
    const bool two = ((POOLK * f) >> 7) != ((POOLK * f + POOLK - 1) >> 7);
    const float* P0 = &g_pool_part[(size_t)f * 2 * B_ROWS];
    const float* P1 = P0 + B_ROWS;
    __shared__ float2 wtot[32];
    float2 carry = make_float2(0.f, 0.f);

    for (int chunk = 0; chunk < B_ROWS / SCT; chunk++) {
        int i = chunk * SCT + t;
        float v = P0[i];
        if (two) v += P1[i];
        v *= (1.0f / (float)POOLK);
        float2 s = make_float2(v, v * v);
        #pragma unroll
        for (int off = 1; off < 32; off <<= 1) {
            float a  = __shfl_up_sync(0xffffffffu, s.x, off);
            float b2 = __shfl_up_sync(0xffffffffu, s.y, off);
            if (lane >= off) { s.x += a; s.y += b2; }
        }
        if (lane == 31) wtot[w] = s;
        __syncthreads();
        if (w == 0) {
            float2 xx = wtot[lane];
            #pragma unroll
            for (int off = 1; off < 32; off <<= 1) {
                float a  = __shfl_up_sync(0xffffffffu, xx.x, off);
                float b2 = __shfl_up_sync(0xffffffffu, xx.y, off);
                if (lane >= off) { xx.x += a; xx.y += b2; }
            }
            wtot[lane] = xx;
        }
        __syncthreads();
        float2 pre = carry;
        if (w > 0) { pre.x += wtot[w - 1].x; pre.y += wtot[w - 1].y; }
        g_cs[i * NF + f] = make_float2(s.x + pre.x, s.y + pre.y);
        carry.x += wtot[31].x;
        carry.y += wtot[31].y;
        __syncthreads();
    }
}

// ------------------------------------------------------------------
// Kernel 3: final — warp per row: sum tile partials + est·WlE + softmax
// ------------------------------------------------------------------
__global__ __launch_bounds__(256) void final_kernel(
    const float* __restrict__ b_lin, float* __restrict__ out)
{
    const int t = threadIdx.x, lane = t & 31, wid = t >> 5;
    __shared__ float est_s[8][272];

    for (int e = t; e < 8 * ESTD; e += 256) {
        int r = e / ESTD, e2 = e % ESTD;
        int f = e2 / 6, rem = e2 % 6, j = rem >> 1, sflag = rem & 1;
        int L = (j == 0) ? 32 : (j == 1) ? 128 : 512;
        int bb = blockIdx.x * 8 + r;
        float2 c1 = g_cs[bb * NF + f];
        float2 c0 = (bb >= L) ? g_cs[(bb - L) * NF + f] : make_float2(0.f, 0.f);
        float cnt = fminf((float)(bb + 1), (float)L);
        float m = (c1.x - c0.x) / cnt;
        est_s[r][e2] = (sflag == 0) ? m : ((c1.y - c0.y) / cnt - m * m);
    }
    __syncthreads();

    const int row = blockIdx.x * 8 + wid;

    float acc[NCLS];
    #pragma unroll
    for (int c = 0; c < NCLS; c++) acc[c] = 0.f;

    if (lane < NTILE) {
        const float* p = &g_lg_part[((size_t)lane * B_ROWS + row) * NCLS];
        #pragma unroll
        for (int c = 0; c < NCLS; c++) acc[c] += p[c];
    }
    for (int e = lane; e < ESTD; e += 32) {
        float ev = est_s[wid][e];
        #pragma unroll
        for (int c = 0; c < NCLS; c++) acc[c] += ev * g_WlE[c * 288 + e];
    }
    #pragma unroll
    for (int c = 0; c < NCLS; c++) {
        #pragma unroll
        for (int off = 16; off > 0; off >>= 1)
            acc[c] += __shfl_down_sync(0xffffffffu, acc[c], off);
    }
    if (lane == 0) {
        float lg[NCLS], mx = -1e30f;
        #pragma unroll
        for (int c = 0; c < NCLS; c++) { lg[c] = acc[c] + b_lin[c]; mx = fmaxf(mx, lg[c]); }
        float sum = 0.f;
        #pragma unroll
        for (int c = 0; c < NCLS; c++) { lg[c] = expf(lg[c] - mx); sum += lg[c]; }
        float inv = 1.0f / sum;
        #pragma unroll
        for (int c = 0; c < NCLS; c++) out[row * NCLS + c] = lg[c] * inv;
    }
}

// ------------------------------------------------------------------
extern "C" void kernel_launch(void* const* d_in, const int* in_sizes, int n_in,
                              void* d_out, int out_size)
{
    (void)in_sizes; (void)n_in; (void)out_size;
    const float* x     = (const float*)d_in[0];
    const float* W_ih  = (const float*)d_in[1];
    // d_in[2] = W_hh — dead: seq_len==1 and h0==0
    const float* b_ih  = (const float*)d_in[3];
    const float* b_hh  = (const float*)d_in[4];
    const float* W_lin = (const float*)d_in[5];
    const float* b_lin = (const float*)d_in[6];
    float* out = (float*)d_out;

    cudaFuncSetAttribute(gemm_tanh_kernel,
                         cudaFuncAttributeMaxDynamicSharedMemorySize, GEMM_SMEM_BYTES);

    __nv_bfloat16 *xb, *wb;
    cudaGetSymbolAddress((void**)&xb, g_xb);
    cudaGetSymbolAddress((void**)&wb, g_wb);

    int nx4 = (B_ROWS * INP) / 4;
    int nw4 = (HID * INP) / 4;

    // GEMM kept as 4th launch (ncu capture slot)
    cvt_bf16_kernel<<<(nx4 + 255) / 256, 256>>>(x, xb, nx4);
    cvt_bf16_kernel<<<(nw4 + 255) / 256, 256>>>(W_ih, wb, nw4);
    prep_wl_kernel<<<(PREP_N + 255) / 256, 256>>>(W_lin);

    dim3 g1(HID / BN, B_ROWS / BM);   // 16 x 64 = 1024 CTAs, 3 per SM
    gemm_tanh_kernel<<<g1, NTHREADS, GEMM_SMEM_BYTES>>>(b_ih, b_hh);

    scan_kernel<<<NF, SCT>>>();
    final_kernel<<<B_ROWS / 8, 256>>>(b_lin, out);
}

// round 15
// speedup vs baseline: 2.1221x; 1.0581x over previous
#include <cuda_runtime.h>
#include <cuda_bf16.h>
#include <cstdint>
#include <math.h>

#define B_ROWS 8192
#define HID    2048
#define INP    2048
#define NCLS   10
#define POOLK  45
#define NF     45
#define ESTD   270
#define WLD    2318   // W_lin leading dim (HID + ESTD)
#define NTILE  (HID / 128)   // 16 N-tiles
#define NTILES_TOT ((B_ROWS / 128) * NTILE)   // 1024 tiles

// ---- GEMM tiling: bf16 m16n8k16, tile 128x128, 4 warps, warp tile 64x64 ----
#define BM 128
#define BN 128
#define BKS 64               // K (bf16 elems) per stage
#define NSTG_IT (INP / BKS)  // 32 stage iterations
#define LDKB 72              // padded bf16 per smem row (144 B)
#define SA_BYTES (BM * LDKB * 2)       // 18432
#define STAGE_BYTES (2 * SA_BYTES)     // 36864 (A + B)
#define GEMM_SMEM_BYTES (2 * STAGE_BYTES)   // 73728 -> 3 CTAs/SM
#define NTHREADS 128          // 4 warps: 2M x 2N, warp tile 64x64
#define GRID_PERSIST 444      // 148 SMs x 3 CTAs

// epilogue smem overlay (floats, within dsm)
#define STG_STRIDE 132
#define SWL_OFF (64 * STG_STRIDE)

// Scratch (device globals — no runtime allocation)
__device__ __nv_bfloat16 g_xb[(size_t)B_ROWS * INP];
__device__ __nv_bfloat16 g_wb[(size_t)HID * INP];
__device__ float  g_Wl[NCLS * HID];
__device__ float  g_WlE[NCLS * 288];
__device__ float  g_lg_part[(size_t)B_ROWS * NTILE * NCLS];   // [row][tile*10]
__device__ float  g_pool_part[(size_t)NF * 2 * B_ROWS];
__device__ float2 g_cs[B_ROWS * NF];
__device__ unsigned g_tile_ctr;

// ------------------------------------------------------------------
__device__ __forceinline__ uint32_t smem_u32(const void* p) {
    return (uint32_t)__cvta_generic_to_shared(p);
}
__device__ __forceinline__ void cp16(uint32_t dst, const void* src) {
    asm volatile("cp.async.cg.shared.global [%0], [%1], 16;\n" :: "r"(dst), "l"(src));
}
__device__ __forceinline__ void ldsm_x4(uint32_t& r0, uint32_t& r1, uint32_t& r2,
                                        uint32_t& r3, uint32_t addr) {
    asm volatile("ldmatrix.sync.aligned.m8n8.x4.shared.b16 {%0,%1,%2,%3}, [%4];"
                 : "=r"(r0), "=r"(r1), "=r"(r2), "=r"(r3) : "r"(addr));
}
__device__ __forceinline__ void mma_bf16(float* d, const uint32_t* a,
                                         uint32_t b0, uint32_t b1) {
    asm volatile(
        "mma.sync.aligned.m16n8k16.row.col.f32.bf16.bf16.f32 "
        "{%0,%1,%2,%3}, {%4,%5,%6,%7}, {%8,%9}, {%0,%1,%2,%3};"
        : "+f"(d[0]), "+f"(d[1]), "+f"(d[2]), "+f"(d[3])
        : "r"(a[0]), "r"(a[1]), "r"(a[2]), "r"(a[3]), "r"(b0), "r"(b1));
}
__device__ __forceinline__ float tanh_fast(float x) {
    float r;
    asm("tanh.approx.f32 %0, %1;" : "=f"(r) : "f"(x));
    return r;
}

// ------------------------------------------------------------------
// Kernel 0: one merged prep — x->bf16, W->bf16, W_lin pack, counter reset
// ------------------------------------------------------------------
#define NX4 ((B_ROWS * INP) / 4)            // 4,194,304
#define NW4 ((HID * INP) / 4)               // 1,048,576
#define XBLK ((NX4 + 255) / 256)            // 16384
#define WBLK ((NW4 + 255) / 256)            // 4096
#define PREP_N (NCLS * HID + NCLS * ESTD)   // 23180
#define PBLK ((PREP_N + 255) / 256)         // 91
__global__ __launch_bounds__(256) void prep_all_kernel(
    const float* __restrict__ x, const float* __restrict__ W_ih,
    const float* __restrict__ Wl)
{
    const int b = blockIdx.x;
    if (b == 0 && threadIdx.x == 0) g_tile_ctr = 0;

    if (b < XBLK) {
        int i = b * 256 + threadIdx.x;
        if (i >= NX4) return;
        float4 v = ((const float4*)x)[i];
        __nv_bfloat162* d2 = (__nv_bfloat162*)g_xb;
        d2[2 * i]     = __floats2bfloat162_rn(v.x, v.y);
        d2[2 * i + 1] = __floats2bfloat162_rn(v.z, v.w);
    } else if (b < XBLK + WBLK) {
        int i = (b - XBLK) * 256 + threadIdx.x;
        if (i >= NW4) return;
        float4 v = ((const float4*)W_ih)[i];
        __nv_bfloat162* d2 = (__nv_bfloat162*)g_wb;
        d2[2 * i]     = __floats2bfloat162_rn(v.x, v.y);
        d2[2 * i + 1] = __floats2bfloat162_rn(v.z, v.w);
    } else {
        int idx = (b - XBLK - WBLK) * 256 + threadIdx.x;
        if (idx >= PREP_N) return;
        int n1 = NCLS * HID;
        if (idx < n1) {
            int c = idx / HID, k = idx % HID;
            g_Wl[idx] = Wl[(size_t)c * WLD + k];
        } else {
            int j = idx - n1;
            int c = j / ESTD, e = j % ESTD;
            g_WlE[c * 288 + e] = Wl[(size_t)c * WLD + HID + e];
        }
    }
}

// ------------------------------------------------------------------
// Kernel 1: PERSISTENT GEMM(bf16) + tanh + fused pool/logits partials
// 444 CTAs, atomic tile work-stealing over 1024 tiles
// ------------------------------------------------------------------
__device__ __forceinline__ void load_stage(char* sbase, int bm, int bn, int kt, int tid)
{
    uint32_t su = smem_u32(sbase);
    #pragma unroll
    for (int i = 0; i < 8; i++) {
        int ci = tid + i * NTHREADS;
        int r = ci >> 3, ko = (ci & 7) << 3;
        cp16(su + (uint32_t)(r * LDKB + ko) * 2,
             g_xb + (size_t)(bm + r) * INP + kt + ko);
    }
    uint32_t sub = su + SA_BYTES;
    #pragma unroll
    for (int i = 0; i < 8; i++) {
        int ci = tid + i * NTHREADS;
        int r = ci >> 3, ko = (ci & 7) << 3;
        cp16(sub + (uint32_t)(r * LDKB + ko) * 2,
             g_wb + (size_t)(bn + r) * INP + kt + ko);
    }
    asm volatile("cp.async.commit_group;" ::: "memory");
}

__global__ __launch_bounds__(NTHREADS, 3) void gemm_tanh_kernel(
    const float* __restrict__ b_ih, const float* __restrict__ b_hh)
{
    extern __shared__ char dsmc[];
    float* dsm = (float*)dsmc;
    __shared__ float sbias[BN];
    __shared__ unsigned s_tile;

    const int tid  = threadIdx.x;
    const int warp = tid >> 5;
    const int lane = tid & 31;
    const int qid  = lane >> 2;
    const int tq   = lane & 3;

    const int wm = (warp & 1) * 64;
    const int wn = (warp >> 1) * 64;

    const uint32_t aoff = (uint32_t)((lane & 15) * LDKB + (lane >> 4) * 8) * 2;
    const uint32_t boff = (uint32_t)((wn + ((lane >> 4) & 1) * 8 + (lane & 7)) * LDKB) * 2
                        + ((lane >> 3) & 1) * 16;

    while (true) {
        if (tid == 0) s_tile = atomicAdd(&g_tile_ctr, 1u);
        __syncthreads();                    // broadcast + protect dsm reuse
        unsigned t = s_tile;
        if (t >= NTILES_TOT) break;
        const int bm = (int)(t >> 4) * BM;
        const int bn = (int)(t & 15) * BN;

        if (tid < BN) sbias[tid] = b_ih[bn + tid] + b_hh[bn + tid];

        float acc[4][8][4];
        #pragma unroll
        for (int mf = 0; mf < 4; mf++)
            #pragma unroll
            for (int nf = 0; nf < 8; nf++)
                #pragma unroll
                for (int e = 0; e < 4; e++) acc[mf][nf][e] = 0.f;

        load_stage(dsmc,               bm, bn, 0,   tid);
        load_stage(dsmc + STAGE_BYTES, bm, bn, BKS, tid);

        for (int s = 0; s < NSTG_IT; s++) {
            if (s >= NSTG_IT - 1)
                asm volatile("cp.async.wait_group 0;" ::: "memory");
            else
                asm volatile("cp.async.wait_group 1;" ::: "memory");
            __syncthreads();

            char* sA = dsmc + (s & 1) * STAGE_BYTES;
            uint32_t sAu = smem_u32(sA);
            uint32_t sBu = sAu + SA_BYTES;

            #pragma unroll
            for (int kk = 0; kk < BKS; kk += 16) {
                uint32_t b[8][2];
                #pragma unroll
                for (int p = 0; p < 4; p++) {
                    uint32_t addr = sBu + boff + (uint32_t)(p * 16 * LDKB * 2) + kk * 2;
                    ldsm_x4(b[2 * p][0], b[2 * p][1], b[2 * p + 1][0], b[2 * p + 1][1], addr);
                }
                #pragma unroll
                for (int mf = 0; mf < 4; mf++) {
                    uint32_t a[4];
                    uint32_t addr = sAu + aoff +
                        (uint32_t)((wm + mf * 16) * LDKB + kk) * 2;
                    ldsm_x4(a[0], a[1], a[2], a[3], addr);
                    #pragma unroll
                    for (int nf = 0; nf < 8; nf++)
                        mma_bf16(acc[mf][nf], a, b[nf][0], b[nf][1]);
                }
            }

            if (s + 2 < NSTG_IT) {
                __syncthreads();
                load_stage(dsmc + (s & 1) * STAGE_BYTES, bm, bn, (s + 2) * BKS, tid);
            }
        }

        // ---------- fused epilogue: two 64-column passes ----------
        float* stg = dsm;
        float* sWl = dsm + SWL_OFF;

        __syncthreads();
        for (int i = tid; i < NCLS * 128; i += NTHREADS)
            sWl[i] = g_Wl[(i >> 7) * HID + bn + (i & 127)];

        const int r = tid;
        const int tileN = bn >> 7;
        int f0 = bn / POOLK;
        int f1 = (bn + 127) / POOLK; if (f1 > NF - 1) f1 = NF - 1;

        float lg[NCLS];
        #pragma unroll
        for (int c = 0; c < NCLS; c++) lg[c] = 0.f;
        float fsum[4] = {0.f, 0.f, 0.f, 0.f};

        for (int pass = 0; pass < 2; pass++) {
            __syncthreads();
            if ((warp >> 1) == pass) {
                #pragma unroll
                for (int mf = 0; mf < 4; mf++) {
                    int r0 = wm + mf * 16 + qid;
                    #pragma unroll
                    for (int nf = 0; nf < 8; nf++) {
                        int lc = nf * 8 + tq * 2;
                        int gc = wn + lc;
                        float b0 = sbias[gc], b1 = sbias[gc + 1];
                        stg[lc * STG_STRIDE + r0]           = tanh_fast(acc[mf][nf][0] + b0);
                        stg[(lc + 1) * STG_STRIDE + r0]     = tanh_fast(acc[mf][nf][1] + b1);
                        stg[lc * STG_STRIDE + r0 + 8]       = tanh_fast(acc[mf][nf][2] + b0);
                        stg[(lc + 1) * STG_STRIDE + r0 + 8] = tanh_fast(acc[mf][nf][3] + b1);
                    }
                }
            }
            __syncthreads();

            const int cbase = pass * 64;
            #pragma unroll 4
            for (int j = 0; j < 64; j++) {
                float y = stg[j * STG_STRIDE + r];
                #pragma unroll
                for (int c = 0; c < NCLS; c++) lg[c] += y * sWl[c * 128 + cbase + j];
            }
            for (int fi = 0; fi <= f1 - f0; fi++) {
                int f = f0 + fi;
                int c0 = POOLK * f - bn, c1 = c0 + POOLK - 1;
                if (c0 < cbase) c0 = cbase;
                if (c1 > cbase + 63) c1 = cbase + 63;
                float sum = 0.f;
                for (int c = c0; c <= c1; c++) sum += stg[(c - cbase) * STG_STRIDE + r];
                fsum[fi] += sum;
            }
        }

        // logits partials: row-major [row][tile*10]
        float* dst = &g_lg_part[((size_t)(bm + r) * NTILE + tileN) * NCLS];
        #pragma unroll
        for (int c = 0; c < NCLS; c++) dst[c] = lg[c];
        for (int fi = 0; fi <= f1 - f0; fi++) {
            int f = f0 + fi;
            int c0 = POOLK * f - bn;
            int c1 = c0 + POOLK - 1;
            if (c0 < 0 || c1 > 127) {
                int slot = (tileN == (POOLK * f) >> 7) ? 0 : 1;
                g_pool_part[((size_t)f * 2 + slot) * B_ROWS + bm + r] = fsum[fi];
            } else {
                g_pool_part[((size_t)f * 2 + 0) * B_ROWS + bm + r] = fsum[fi];
            }
        }
        // loop top __syncthreads orders stg reads vs next tile's cp.async
    }
}

// ------------------------------------------------------------------
// Kernel 2: per-feature inclusive scan, 1024 threads (8 chunks)
// ------------------------------------------------------------------
#define SCT 1024
__global__ __launch_bounds__(SCT) void scan_kernel()
{
    const int f = blockIdx.x;
    const int t = threadIdx.x, lane = t & 31, w = t >> 5;
    const bool two = ((POOLK * f) >> 7) != ((POOLK * f + POOLK - 1) >> 7);
    const float* P0 = &g_pool_part[(size_t)f * 2 * B_ROWS];
    const float* P1 = P0 + B_ROWS;
    __shared__ float2 wtot[32];
    float2 carry = make_float2(0.f, 0.f);

    for (int chunk = 0; chunk < B_ROWS / SCT; chunk++) {
        int i = chunk * SCT + t;
        float v = P0[i];
        if (two) v += P1[i];
        v *= (1.0f / (float)POOLK);
        float2 s = make_float2(v, v * v);
        #pragma unroll
        for (int off = 1; off < 32; off <<= 1) {
            float a  = __shfl_up_sync(0xffffffffu, s.x, off);
            float b2 = __shfl_up_sync(0xffffffffu, s.y, off);
            if (lane >= off) { s.x += a; s.y += b2; }
        }
        if (lane == 31) wtot[w] = s;
        __syncthreads();
        if (w == 0) {
            float2 xx = wtot[lane];
            #pragma unroll
            for (int off = 1; off < 32; off <<= 1) {
                float a  = __shfl_up_sync(0xffffffffu, xx.x, off);
                float b2 = __shfl_up_sync(0xffffffffu, xx.y, off);
                if (lane >= off) { xx.x += a; xx.y += b2; }
            }
            wtot[lane] = xx;
        }
        __syncthreads();
        float2 pre = carry;
        if (w > 0) { pre.x += wtot[w - 1].x; pre.y += wtot[w - 1].y; }
        g_cs[i * NF + f] = make_float2(s.x + pre.x, s.y + pre.y);
        carry.x += wtot[31].x;
        carry.y += wtot[31].y;
        __syncthreads();
    }
}

// ------------------------------------------------------------------
// Kernel 3: final — warp per row: sum tile partials + est·WlE + softmax
// ------------------------------------------------------------------
__global__ __launch_bounds__(256) void final_kernel(
    const float* __restrict__ b_lin, float* __restrict__ out)
{
    const int t = threadIdx.x, lane = t & 31, wid = t >> 5;
    __shared__ float est_s[8][272];

    for (int e = t; e < 8 * ESTD; e += 256) {
        int r = e / ESTD, e2 = e % ESTD;
        int f = e2 / 6, rem = e2 % 6, j = rem >> 1, sflag = rem & 1;
        int L = (j == 0) ? 32 : (j == 1) ? 128 : 512;
        int bb = blockIdx.x * 8 + r;
        float2 c1 = g_cs[bb * NF + f];
        float2 c0 = (bb >= L) ? g_cs[(bb - L) * NF + f] : make_float2(0.f, 0.f);
        float cnt = fminf((float)(bb + 1), (float)L);
        float m = (c1.x - c0.x) / cnt;
        est_s[r][e2] = (sflag == 0) ? m : ((c1.y - c0.y) / cnt - m * m);
    }
    __syncthreads();

    const int row = blockIdx.x * 8 + wid;

    float acc[NCLS];
    #pragma unroll
    for (int c = 0; c < NCLS; c++) acc[c] = 0.f;

    // contiguous row of 160 partials; 16 lanes x 10 floats
    if (lane < NTILE) {
        const float* p = &g_lg_part[((size_t)row * NTILE + lane) * NCLS];
        #pragma unroll
        for (int c = 0; c < NCLS; c++) acc[c] += p[c];
    }
    for (int e = lane; e < ESTD; e += 32) {
        float ev = est_s[wid][e];
        #pragma unroll
        for (int c = 0; c < NCLS; c++) acc[c] += ev * g_WlE[c * 288 + e];
    }
    #pragma unroll
    for (int c = 0; c < NCLS; c++) {
        #pragma unroll
        for (int off = 16; off > 0; off >>= 1)
            acc[c] += __shfl_down_sync(0xffffffffu, acc[c], off);
    }
    if (lane == 0) {
        float lg[NCLS], mx = -1e30f;
        #pragma unroll
        for (int c = 0; c < NCLS; c++) { lg[c] = acc[c] + b_lin[c]; mx = fmaxf(mx, lg[c]); }
        float sum = 0.f;
        #pragma unroll
        for (int c = 0; c < NCLS; c++) { lg[c] = expf(lg[c] - mx); sum += lg[c]; }
        float inv = 1.0f / sum;
        #pragma unroll
        for (int c = 0; c < NCLS; c++) out[row * NCLS + c] = lg[c] * inv;
    }
}

// ------------------------------------------------------------------
extern "C" void kernel_launch(void* const* d_in, const int* in_sizes, int n_in,
                              void* d_out, int out_size)
{
    (void)in_sizes; (void)n_in; (void)out_size;
    const float* x     = (const float*)d_in[0];
    const float* W_ih  = (const float*)d_in[1];
    // d_in[2] = W_hh — dead: seq_len==1 and h0==0
    const float* b_ih  = (const float*)d_in[3];
    const float* b_hh  = (const float*)d_in[4];
    const float* W_lin = (const float*)d_in[5];
    const float* b_lin = (const float*)d_in[6];
    float* out = (float*)d_out;

    cudaFuncSetAttribute(gemm_tanh_kernel,
                         cudaFuncAttributeMaxDynamicSharedMemorySize, GEMM_SMEM_BYTES);

    prep_all_kernel<<<XBLK + WBLK + PBLK, 256>>>(x, W_ih, W_lin);
    gemm_tanh_kernel<<<GRID_PERSIST, NTHREADS, GEMM_SMEM_BYTES>>>(b_ih, b_hh);
    scan_kernel<<<NF, SCT>>>();
    final_kernel<<<B_ROWS / 8, 256>>>(b_lin, out);
}